// round 1
// baseline (speedup 1.0000x reference)
#include <cuda_runtime.h>
#include <cuda_bf16.h>
#include <stdint.h>

// ---------------------------------------------------------------------------
// Problem constants (shapes fixed by the dataset)
// ---------------------------------------------------------------------------
#define NMAX 100000
#define EMAX 3200000
#define F0 512
#define F1 256
#define F2 64

// ---------------------------------------------------------------------------
// Static device scratch (allocation-free rule: __device__ globals)
// ---------------------------------------------------------------------------
__device__ float d_xw1[NMAX * F1];     // x @ W1            [N,256]  102.4 MB
__device__ float d_h[NMAX * F1];       // relu(spmm1)       [N,256]  102.4 MB
__device__ float d_hw2[NMAX * F2];     // relu(bn1(h)) @ W2 [N,64]    25.6 MB
__device__ int   d_cnt[NMAX];
__device__ int   d_fill[NMAX];
__device__ int   d_rowptr[NMAX + 1];
__device__ int   d_cols[EMAX];
__device__ float d_vals[EMAX];
__device__ int   d_chunksums[128];
__device__ float d_sum1[F1], d_sumsq1[F1], d_scale1[F1], d_bias1[F1];
__device__ float d_sum2[F2], d_sumsq2[F2], d_scale2[F2], d_bias2[F2];

// ---------------------------------------------------------------------------
// Zero transient accumulators (graph replays reuse the globals)
// ---------------------------------------------------------------------------
__global__ void zero_kernel(int Nn) {
    int i = blockIdx.x * blockDim.x + threadIdx.x;
    if (i < Nn) { d_cnt[i] = 0; d_fill[i] = 0; }
    if (i < F1) { d_sum1[i] = 0.f; d_sumsq1[i] = 0.f; }
    if (i < F2) { d_sum2[i] = 0.f; d_sumsq2[i] = 0.f; }
}

// ---------------------------------------------------------------------------
// CSR build: histogram -> 2-level exclusive scan -> scatter
// ---------------------------------------------------------------------------
__global__ void hist_kernel(const int* __restrict__ erow, int E) {
    int i = blockIdx.x * blockDim.x + threadIdx.x;
    if (i < E) atomicAdd(&d_cnt[erow[i]], 1);
}

__global__ void scanA_kernel(int Nn) {
    __shared__ int sh[1024];
    int gid = blockIdx.x * 1024 + threadIdx.x;
    int v = (gid < Nn) ? d_cnt[gid] : 0;
    sh[threadIdx.x] = v;
    __syncthreads();
#pragma unroll
    for (int off = 1; off < 1024; off <<= 1) {
        int t = (threadIdx.x >= off) ? sh[threadIdx.x - off] : 0;
        __syncthreads();
        sh[threadIdx.x] += t;
        __syncthreads();
    }
    if (gid < Nn) d_rowptr[gid] = sh[threadIdx.x] - v;   // exclusive, chunk-local
    if (threadIdx.x == 1023) d_chunksums[blockIdx.x] = sh[1023];
}

__global__ void scanB_kernel(int nch) {
    __shared__ int sh[128];
    int v = (threadIdx.x < nch) ? d_chunksums[threadIdx.x] : 0;
    sh[threadIdx.x] = v;
    __syncthreads();
#pragma unroll
    for (int off = 1; off < 128; off <<= 1) {
        int t = (threadIdx.x >= off) ? sh[threadIdx.x - off] : 0;
        __syncthreads();
        sh[threadIdx.x] += t;
        __syncthreads();
    }
    if (threadIdx.x < nch) d_chunksums[threadIdx.x] = sh[threadIdx.x] - v;  // exclusive
}

__global__ void scanC_kernel(int Nn, int E) {
    int gid = blockIdx.x * blockDim.x + threadIdx.x;
    if (gid < Nn) d_rowptr[gid] += d_chunksums[gid >> 10];
    if (gid == 0) d_rowptr[Nn] = E;
}

__global__ void scatter_kernel(const int* __restrict__ erow,
                               const int* __restrict__ ecol,
                               const float* __restrict__ eval, int E) {
    int i = blockIdx.x * blockDim.x + threadIdx.x;
    if (i < E) {
        int r = erow[i];
        int p = d_rowptr[r] + atomicAdd(&d_fill[r], 1);
        d_cols[p] = ecol[i];
        d_vals[p] = eval[i];
    }
}

// ---------------------------------------------------------------------------
// GEMM1: xw1 = x @ W1   (M x 512) x (512 x 256), fp32 tiled
// Tile 128x64x16, 256 threads, 8x4 per thread.
// ---------------------------------------------------------------------------
__global__ void gemm1_kernel(const float* __restrict__ A,
                             const float* __restrict__ B, int M) {
    __shared__ float As[16][128];
    __shared__ float Bs[16][64];
    const int tid = threadIdx.x;
    const int bm0 = blockIdx.x * 128;
    const int bn0 = blockIdx.y * 64;
    const int tx = tid & 15, ty = tid >> 4;
    const int ar = tid >> 2, ac = (tid & 3) * 4;     // A-load: 2 rows of float4
    const int br = tid >> 4, bc = (tid & 15) * 4;    // B-load: 1 float4

    float acc[8][4];
#pragma unroll
    for (int i = 0; i < 8; i++)
#pragma unroll
        for (int j = 0; j < 4; j++) acc[i][j] = 0.f;

    for (int k0 = 0; k0 < F0; k0 += 16) {
#pragma unroll
        for (int h = 0; h < 2; h++) {
            int row = bm0 + ar + h * 64;
            float4 a = make_float4(0.f, 0.f, 0.f, 0.f);
            if (row < M) a = *(const float4*)(A + (size_t)row * F0 + k0 + ac);
            As[ac + 0][ar + h * 64] = a.x;
            As[ac + 1][ar + h * 64] = a.y;
            As[ac + 2][ar + h * 64] = a.z;
            As[ac + 3][ar + h * 64] = a.w;
        }
        float4 b = *(const float4*)(B + (size_t)(k0 + br) * F1 + bn0 + bc);
        *(float4*)&Bs[br][bc] = b;
        __syncthreads();
#pragma unroll
        for (int k = 0; k < 16; k++) {
            float areg[8];
            float4 breg = *(float4*)&Bs[k][tx * 4];
#pragma unroll
            for (int i = 0; i < 8; i++) areg[i] = As[k][ty + i * 16];
#pragma unroll
            for (int i = 0; i < 8; i++) {
                acc[i][0] = fmaf(areg[i], breg.x, acc[i][0]);
                acc[i][1] = fmaf(areg[i], breg.y, acc[i][1]);
                acc[i][2] = fmaf(areg[i], breg.z, acc[i][2]);
                acc[i][3] = fmaf(areg[i], breg.w, acc[i][3]);
            }
        }
        __syncthreads();
    }
#pragma unroll
    for (int i = 0; i < 8; i++) {
        int row = bm0 + ty + i * 16;
        if (row < M) {
            float4 v = make_float4(acc[i][0], acc[i][1], acc[i][2], acc[i][3]);
            *(float4*)(d_xw1 + (size_t)row * F1 + bn0 + tx * 4) = v;
        }
    }
}

// ---------------------------------------------------------------------------
// SpMM1: h = relu(A_sparse @ xw1), warp-per-row, 8 f32 per lane
// ---------------------------------------------------------------------------
__global__ void spmm1_kernel(int Nn) {
    int warp = (blockIdx.x * blockDim.x + threadIdx.x) >> 5;
    int lane = threadIdx.x & 31;
    if (warp >= Nn) return;
    int s = d_rowptr[warp], e = d_rowptr[warp + 1];
    float4 a0 = make_float4(0.f, 0.f, 0.f, 0.f);
    float4 a1 = make_float4(0.f, 0.f, 0.f, 0.f);
    for (int i = s; i < e; i++) {
        int c = __ldg(&d_cols[i]);
        float v = __ldg(&d_vals[i]);
        const float4* p = (const float4*)(d_xw1 + (size_t)c * F1);
        float4 x0 = __ldg(&p[lane]);
        float4 x1 = __ldg(&p[lane + 32]);
        a0.x = fmaf(v, x0.x, a0.x); a0.y = fmaf(v, x0.y, a0.y);
        a0.z = fmaf(v, x0.z, a0.z); a0.w = fmaf(v, x0.w, a0.w);
        a1.x = fmaf(v, x1.x, a1.x); a1.y = fmaf(v, x1.y, a1.y);
        a1.z = fmaf(v, x1.z, a1.z); a1.w = fmaf(v, x1.w, a1.w);
    }
    float4* o = (float4*)(d_h + (size_t)warp * F1);
    o[lane]      = make_float4(fmaxf(a0.x, 0.f), fmaxf(a0.y, 0.f),
                               fmaxf(a0.z, 0.f), fmaxf(a0.w, 0.f));
    o[lane + 32] = make_float4(fmaxf(a1.x, 0.f), fmaxf(a1.y, 0.f),
                               fmaxf(a1.z, 0.f), fmaxf(a1.w, 0.f));
}

// ---------------------------------------------------------------------------
// BN stats: per-column sum / sumsq (column == threadIdx.x, coalesced)
// ---------------------------------------------------------------------------
__global__ void bnstats_kernel(const float* __restrict__ h, float* __restrict__ sum,
                               float* __restrict__ sumsq, int Nn, int F) {
    int col = threadIdx.x;
    float s = 0.f, s2 = 0.f;
    for (int r = blockIdx.x; r < Nn; r += gridDim.x) {
        float v = h[(size_t)r * F + col];
        s += v;
        s2 = fmaf(v, v, s2);
    }
    atomicAdd(&sum[col], s);
    atomicAdd(&sumsq[col], s2);
}

__global__ void bnfin_kernel(const float* __restrict__ sum, const float* __restrict__ sumsq,
                             const float* __restrict__ gamma, const float* __restrict__ beta,
                             float* __restrict__ scale, float* __restrict__ bias,
                             int Nn, int F) {
    int c = threadIdx.x;
    if (c >= F) return;
    float inv = 1.f / (float)Nn;
    float mean = sum[c] * inv;
    float var = sumsq[c] * inv - mean * mean;
    float rs = rsqrtf(var + 1e-5f);
    float sc = gamma[c] * rs;
    scale[c] = sc;
    bias[c] = beta[c] - mean * sc;
}

// ---------------------------------------------------------------------------
// GEMM2: hw2 = relu(bn1(h)) @ W2   (M x 256) x (256 x 64)
// BN1 affine + ReLU fused into the A-tile load. Tile 128x64x16.
// ---------------------------------------------------------------------------
__global__ void gemm2_kernel(const float* __restrict__ B, int M) {
    __shared__ float As[16][128];
    __shared__ float Bs[16][64];
    __shared__ float s_sc[F1], s_bi[F1];
    const int tid = threadIdx.x;
    s_sc[tid] = d_scale1[tid];
    s_bi[tid] = d_bias1[tid];
    const int bm0 = blockIdx.x * 128;
    const int tx = tid & 15, ty = tid >> 4;
    const int ar = tid >> 2, ac = (tid & 3) * 4;
    const int br = tid >> 4, bc = (tid & 15) * 4;

    float acc[8][4];
#pragma unroll
    for (int i = 0; i < 8; i++)
#pragma unroll
        for (int j = 0; j < 4; j++) acc[i][j] = 0.f;
    __syncthreads();

    for (int k0 = 0; k0 < F1; k0 += 16) {
#pragma unroll
        for (int h = 0; h < 2; h++) {
            int row = bm0 + ar + h * 64;
            float4 a = make_float4(0.f, 0.f, 0.f, 0.f);
            if (row < M) {
                a = *(const float4*)(d_h + (size_t)row * F1 + k0 + ac);
                a.x = fmaxf(fmaf(a.x, s_sc[k0 + ac + 0], s_bi[k0 + ac + 0]), 0.f);
                a.y = fmaxf(fmaf(a.y, s_sc[k0 + ac + 1], s_bi[k0 + ac + 1]), 0.f);
                a.z = fmaxf(fmaf(a.z, s_sc[k0 + ac + 2], s_bi[k0 + ac + 2]), 0.f);
                a.w = fmaxf(fmaf(a.w, s_sc[k0 + ac + 3], s_bi[k0 + ac + 3]), 0.f);
            }
            As[ac + 0][ar + h * 64] = a.x;
            As[ac + 1][ar + h * 64] = a.y;
            As[ac + 2][ar + h * 64] = a.z;
            As[ac + 3][ar + h * 64] = a.w;
        }
        float4 b = *(const float4*)(B + (size_t)(k0 + br) * F2 + bc);
        *(float4*)&Bs[br][bc] = b;
        __syncthreads();
#pragma unroll
        for (int k = 0; k < 16; k++) {
            float areg[8];
            float4 breg = *(float4*)&Bs[k][tx * 4];
#pragma unroll
            for (int i = 0; i < 8; i++) areg[i] = As[k][ty + i * 16];
#pragma unroll
            for (int i = 0; i < 8; i++) {
                acc[i][0] = fmaf(areg[i], breg.x, acc[i][0]);
                acc[i][1] = fmaf(areg[i], breg.y, acc[i][1]);
                acc[i][2] = fmaf(areg[i], breg.z, acc[i][2]);
                acc[i][3] = fmaf(areg[i], breg.w, acc[i][3]);
            }
        }
        __syncthreads();
    }
#pragma unroll
    for (int i = 0; i < 8; i++) {
        int row = bm0 + ty + i * 16;
        if (row < M) {
            float4 v = make_float4(acc[i][0], acc[i][1], acc[i][2], acc[i][3]);
            *(float4*)(d_hw2 + (size_t)row * F2 + tx * 4) = v;
        }
    }
}

// ---------------------------------------------------------------------------
// SpMM2: out = relu(A_sparse @ hw2), warp-per-row, float2 per lane
// ---------------------------------------------------------------------------
__global__ void spmm2_kernel(float* __restrict__ out, int Nn) {
    int warp = (blockIdx.x * blockDim.x + threadIdx.x) >> 5;
    int lane = threadIdx.x & 31;
    if (warp >= Nn) return;
    int s = d_rowptr[warp], e = d_rowptr[warp + 1];
    float2 acc = make_float2(0.f, 0.f);
    for (int i = s; i < e; i++) {
        int c = __ldg(&d_cols[i]);
        float v = __ldg(&d_vals[i]);
        const float2* p = (const float2*)(d_hw2 + (size_t)c * F2);
        float2 x0 = __ldg(&p[lane]);
        acc.x = fmaf(v, x0.x, acc.x);
        acc.y = fmaf(v, x0.y, acc.y);
    }
    float2* o = (float2*)(out + (size_t)warp * F2);
    o[lane] = make_float2(fmaxf(acc.x, 0.f), fmaxf(acc.y, 0.f));
}

// ---------------------------------------------------------------------------
// BN2 apply in place on d_out
// ---------------------------------------------------------------------------
__global__ void bnapply2_kernel(float* __restrict__ out, int total) {
    int i = blockIdx.x * blockDim.x + threadIdx.x;
    if (i < total) {
        int c = i & (F2 - 1);
        out[i] = fmaf(out[i], d_scale2[c], d_bias2[c]);
    }
}

// ---------------------------------------------------------------------------
// Launch sequence (graph-capturable: kernel launches only, default stream)
// ---------------------------------------------------------------------------
extern "C" void kernel_launch(void* const* d_in, const int* in_sizes, int n_in,
                              void* d_out, int out_size) {
    const float* x    = (const float*)d_in[0];
    const int*   erow = (const int*)d_in[1];
    const int*   ecol = (const int*)d_in[2];
    const float* evl  = (const float*)d_in[3];
    const float* W1   = (const float*)d_in[4];
    const float* g1   = (const float*)d_in[5];
    const float* b1   = (const float*)d_in[6];
    const float* W2   = (const float*)d_in[7];
    const float* g2   = (const float*)d_in[8];
    const float* b2   = (const float*)d_in[9];
    float* out = (float*)d_out;

    const int Nn = in_sizes[0] / F0;   // 100000
    const int E  = in_sizes[1];        // 3200000
    const int nch = (Nn + 1023) / 1024;

    float* p_sum1   = nullptr; cudaGetSymbolAddress((void**)&p_sum1,   d_sum1);
    float* p_sumsq1 = nullptr; cudaGetSymbolAddress((void**)&p_sumsq1, d_sumsq1);
    float* p_scale1 = nullptr; cudaGetSymbolAddress((void**)&p_scale1, d_scale1);
    float* p_bias1  = nullptr; cudaGetSymbolAddress((void**)&p_bias1,  d_bias1);
    float* p_sum2   = nullptr; cudaGetSymbolAddress((void**)&p_sum2,   d_sum2);
    float* p_sumsq2 = nullptr; cudaGetSymbolAddress((void**)&p_sumsq2, d_sumsq2);
    float* p_scale2 = nullptr; cudaGetSymbolAddress((void**)&p_scale2, d_scale2);
    float* p_bias2  = nullptr; cudaGetSymbolAddress((void**)&p_bias2,  d_bias2);
    float* p_h      = nullptr; cudaGetSymbolAddress((void**)&p_h,      d_h);

    // CSR build
    zero_kernel<<<(Nn + 255) / 256, 256>>>(Nn);
    hist_kernel<<<(E + 255) / 256, 256>>>(erow, E);
    scanA_kernel<<<nch, 1024>>>(Nn);
    scanB_kernel<<<1, 128>>>(nch);
    scanC_kernel<<<(Nn + 255) / 256, 256>>>(Nn, E);
    scatter_kernel<<<(E + 255) / 256, 256>>>(erow, ecol, evl, E);

    // Layer 1
    gemm1_kernel<<<dim3((Nn + 127) / 128, F1 / 64), 256>>>(x, W1, Nn);
    spmm1_kernel<<<(Nn + 7) / 8, 256>>>(Nn);
    bnstats_kernel<<<784, F1>>>(p_h, p_sum1, p_sumsq1, Nn, F1);
    bnfin_kernel<<<1, F1>>>(p_sum1, p_sumsq1, g1, b1, p_scale1, p_bias1, Nn, F1);

    // Layer 2 (BN1+ReLU fused into GEMM2's A load)
    gemm2_kernel<<<dim3((Nn + 127) / 128, 1), 256>>>(W2, Nn);
    spmm2_kernel<<<(Nn + 7) / 8, 256>>>(out, Nn);
    bnstats_kernel<<<784, F2>>>(out, p_sum2, p_sumsq2, Nn, F2);
    bnfin_kernel<<<1, F2>>>(p_sum2, p_sumsq2, g2, b2, p_scale2, p_bias2, Nn, F2);
    bnapply2_kernel<<<(Nn * F2 + 255) / 256, 256>>>(out, Nn * F2);
}

// round 4
// speedup vs baseline: 1.3789x; 1.3789x over previous
#include <cuda_runtime.h>
#include <cuda_bf16.h>
#include <stdint.h>

// ---------------------------------------------------------------------------
// Problem constants
// ---------------------------------------------------------------------------
#define NMAX 100000
#define EMAX 3200000
#define F0 512
#define F1 256
#define F2 64

// ---------------------------------------------------------------------------
// Static device scratch
// ---------------------------------------------------------------------------
__device__ float d_xw1[NMAX * F1];
__device__ float d_h[NMAX * F1];
__device__ float d_hw2[NMAX * F2];
__device__ int   d_cnt[NMAX];
__device__ int   d_fill[NMAX];
__device__ int   d_rowptr[NMAX + 1];
__device__ int   d_cols[EMAX];
__device__ float d_vals[EMAX];
__device__ int   d_chunksums[128];
__device__ float d_sum1[F1], d_sumsq1[F1], d_scale1[F1], d_bias1[F1];
__device__ float d_sum2[F2], d_sumsq2[F2], d_scale2[F2], d_bias2[F2];
// W1 split into bf16 [hi | lo | hi] along K, layout [N=256][Keff=1536] K-major
__device__ __align__(128) __nv_bfloat16 d_Bcat[F1 * (3 * F0)];

// ---------------------------------------------------------------------------
// Helpers
// ---------------------------------------------------------------------------
__device__ __forceinline__ uint32_t smem_u32(const void* p) {
    uint32_t a;
    asm("{ .reg .u64 t; cvta.to.shared.u64 t, %1; cvt.u32.u64 %0, t; }" : "=r"(a) : "l"(p));
    return a;
}
__device__ __forceinline__ uint32_t pack2hi(float a, float b) {
    __nv_bfloat162 t = __floats2bfloat162_rn(a, b);
    return *(uint32_t*)&t;
}
__device__ __forceinline__ uint32_t pack2lo(float a, float b) {
    float ah = __bfloat162float(__float2bfloat16_rn(a));
    float bh = __bfloat162float(__float2bfloat16_rn(b));
    __nv_bfloat162 t = __floats2bfloat162_rn(a - ah, b - bh);
    return *(uint32_t*)&t;
}
__device__ __forceinline__ void mma_bf16(float* d, const uint32_t* a, uint32_t b0, uint32_t b1) {
    asm volatile(
        "mma.sync.aligned.m16n8k16.row.col.f32.bf16.bf16.f32 "
        "{%0,%1,%2,%3}, {%4,%5,%6,%7}, {%8,%9}, {%0,%1,%2,%3};"
        : "+f"(d[0]), "+f"(d[1]), "+f"(d[2]), "+f"(d[3])
        : "r"(a[0]), "r"(a[1]), "r"(a[2]), "r"(a[3]), "r"(b0), "r"(b1));
}
__device__ __forceinline__ void ldmatrix_x4(uint32_t* r, uint32_t addr) {
    asm volatile("ldmatrix.sync.aligned.m8n8.x4.shared.b16 {%0,%1,%2,%3}, [%4];"
                 : "=r"(r[0]), "=r"(r[1]), "=r"(r[2]), "=r"(r[3]) : "r"(addr));
}

// ---------------------------------------------------------------------------
// Zero transient accumulators
// ---------------------------------------------------------------------------
__global__ void zero_kernel(int Nn) {
    int i = blockIdx.x * blockDim.x + threadIdx.x;
    if (i < Nn) { d_cnt[i] = 0; d_fill[i] = 0; }
    if (i < F1) { d_sum1[i] = 0.f; d_sumsq1[i] = 0.f; }
    if (i < F2) { d_sum2[i] = 0.f; d_sumsq2[i] = 0.f; }
}

// ---------------------------------------------------------------------------
// CSR build
// ---------------------------------------------------------------------------
__global__ void hist_kernel(const int* __restrict__ erow, int E) {
    int i = blockIdx.x * blockDim.x + threadIdx.x;
    if (i < E) atomicAdd(&d_cnt[erow[i]], 1);
}

__global__ void scanA_kernel(int Nn) {
    __shared__ int sh[1024];
    int gid = blockIdx.x * 1024 + threadIdx.x;
    int v = (gid < Nn) ? d_cnt[gid] : 0;
    sh[threadIdx.x] = v;
    __syncthreads();
#pragma unroll
    for (int off = 1; off < 1024; off <<= 1) {
        int t = (threadIdx.x >= off) ? sh[threadIdx.x - off] : 0;
        __syncthreads();
        sh[threadIdx.x] += t;
        __syncthreads();
    }
    if (gid < Nn) d_rowptr[gid] = sh[threadIdx.x] - v;
    if (threadIdx.x == 1023) d_chunksums[blockIdx.x] = sh[1023];
}

__global__ void scanB_kernel(int nch) {
    __shared__ int sh[128];
    int v = (threadIdx.x < nch) ? d_chunksums[threadIdx.x] : 0;
    sh[threadIdx.x] = v;
    __syncthreads();
#pragma unroll
    for (int off = 1; off < 128; off <<= 1) {
        int t = (threadIdx.x >= off) ? sh[threadIdx.x - off] : 0;
        __syncthreads();
        sh[threadIdx.x] += t;
        __syncthreads();
    }
    if (threadIdx.x < nch) d_chunksums[threadIdx.x] = sh[threadIdx.x] - v;
}

__global__ void scanC_kernel(int Nn, int E) {
    int gid = blockIdx.x * blockDim.x + threadIdx.x;
    if (gid < Nn) d_rowptr[gid] += d_chunksums[gid >> 10];
    if (gid == 0) d_rowptr[Nn] = E;
}

__global__ void scatter_kernel(const int* __restrict__ erow,
                               const int* __restrict__ ecol,
                               const float* __restrict__ eval, int E) {
    int i = blockIdx.x * blockDim.x + threadIdx.x;
    if (i < E) {
        int r = erow[i];
        int p = d_rowptr[r] + atomicAdd(&d_fill[r], 1);
        d_cols[p] = ecol[i];
        d_vals[p] = eval[i];
    }
}

// ---------------------------------------------------------------------------
// Prep: split W1 (512x256 fp32) into d_Bcat[n][1536] = [hi | lo | hi] bf16
// ---------------------------------------------------------------------------
__global__ void prepW1_kernel(const float* __restrict__ W1) {
    int i = blockIdx.x * blockDim.x + threadIdx.x;
    if (i >= F0 * F1) return;
    int k = i >> 8;        // 0..511
    int n = i & 255;       // 0..255
    float w = W1[i];
    __nv_bfloat16 h = __float2bfloat16_rn(w);
    __nv_bfloat16 l = __float2bfloat16_rn(w - __bfloat162float(h));
    d_Bcat[(size_t)n * 1536 + k] = h;
    d_Bcat[(size_t)n * 1536 + 512 + k] = l;
    d_Bcat[(size_t)n * 1536 + 1024 + k] = h;
}

// ---------------------------------------------------------------------------
// GEMM1 via mma.sync bf16 (HMMA), split-bf16 3-term: xw1 = x @ W1
// Block tile 128x128, warp tile 32x64 (4x2 warps), K-chunk 32, Keff=1536.
// SMEM pitch 40 bf16 (80B): conflict-free ldmatrix + LDS.32.
// ---------------------------------------------------------------------------
#define PITCHB 80           // bytes per SMEM row (40 bf16)
#define CHUNKS 48           // 1536 / 32

__global__ void __launch_bounds__(256, 2)
gemm1_mma_kernel(const float* __restrict__ x, int M) {
    __shared__ __align__(16) char smA[2][128 * PITCHB];
    __shared__ __align__(16) char smB[2][128 * PITCHB];

    const int tid = threadIdx.x;
    const int wid = tid >> 5;
    const int lane = tid & 31;
    const int warp_m = wid & 3;        // 0..3 -> 32-row slices
    const int warp_n = wid >> 2;       // 0..1 -> 64-col slices
    const int gid = lane >> 2;         // 0..7
    const int tg = lane & 3;           // 0..3
    const int bm0 = blockIdx.x * 128;
    const int bn0 = blockIdx.y * 128;

    float acc[2][8][4];
#pragma unroll
    for (int mt = 0; mt < 2; mt++)
#pragma unroll
        for (int nt = 0; nt < 8; nt++)
#pragma unroll
            for (int q = 0; q < 4; q++) acc[mt][nt][q] = 0.f;

    // ---- prologue: fill buffer 0 (chunk 0: pass=0 -> hi)
    {
#pragma unroll
        for (int i = 0; i < 4; i++) {
            int idx = tid + i * 256;
            int row = idx >> 3, f4 = idx & 7;
            int rg = bm0 + row;
            float4 f = make_float4(0.f, 0.f, 0.f, 0.f);
            if (rg < M) f = *(const float4*)(x + (size_t)rg * F0 + f4 * 4);
            *(uint2*)(smA[0] + row * PITCHB + f4 * 8) =
                make_uint2(pack2hi(f.x, f.y), pack2hi(f.z, f.w));
        }
#pragma unroll
        for (int i = 0; i < 2; i++) {
            int idx = tid + i * 256;
            int row = idx >> 2, q = idx & 3;
            uint4 v = *(const uint4*)((const char*)d_Bcat +
                                      (size_t)(bn0 + row) * 3072 + q * 16);
            *(uint4*)(smB[0] + row * PITCHB + q * 16) = v;
        }
    }
    __syncthreads();

    for (int c = 0; c < CHUNKS; c++) {
        const int buf = c & 1;
        // ---- stage chunk c+1 into registers (overlaps with compute)
        uint2 sa[4];
        uint4 sb[2];
        const int cn = c + 1;
        if (cn < CHUNKS) {
            const int pass = cn >> 4;
            const int sk0 = (cn & 15) * 32;
            const bool wantlo = (pass == 2);
#pragma unroll
            for (int i = 0; i < 4; i++) {
                int idx = tid + i * 256;
                int row = idx >> 3, f4 = idx & 7;
                int rg = bm0 + row;
                float4 f = make_float4(0.f, 0.f, 0.f, 0.f);
                if (rg < M) f = *(const float4*)(x + (size_t)rg * F0 + sk0 + f4 * 4);
                if (!wantlo) sa[i] = make_uint2(pack2hi(f.x, f.y), pack2hi(f.z, f.w));
                else         sa[i] = make_uint2(pack2lo(f.x, f.y), pack2lo(f.z, f.w));
            }
#pragma unroll
            for (int i = 0; i < 2; i++) {
                int idx = tid + i * 256;
                int row = idx >> 2, q = idx & 3;
                sb[i] = *(const uint4*)((const char*)d_Bcat +
                                        (size_t)(bn0 + row) * 3072 + (size_t)cn * 64 + q * 16);
            }
        }
        // ---- compute on buf
        const uint32_t sA = smem_u32(smA[buf]);
        const char* Bbase = smB[buf];
#pragma unroll
        for (int ks = 0; ks < 2; ks++) {
            uint32_t afrag[2][4];
#pragma unroll
            for (int mt = 0; mt < 2; mt++) {
                uint32_t addr = sA + (warp_m * 32 + mt * 16 + (lane & 15)) * PITCHB
                                + ks * 32 + (lane >> 4) * 16;
                ldmatrix_x4(afrag[mt], addr);
            }
#pragma unroll
            for (int nt = 0; nt < 8; nt++) {
                const char* bp = Bbase + (warp_n * 64 + nt * 8 + gid) * PITCHB
                                 + ks * 32 + tg * 4;
                uint32_t b0 = *(const uint32_t*)bp;
                uint32_t b1 = *(const uint32_t*)(bp + 16);
                mma_bf16(acc[0][nt], afrag[0], b0, b1);
                mma_bf16(acc[1][nt], afrag[1], b0, b1);
            }
        }
        // ---- commit staged chunk to the other buffer
        if (cn < CHUNKS) {
            char* dA = smA[buf ^ 1];
            char* dB = smB[buf ^ 1];
#pragma unroll
            for (int i = 0; i < 4; i++) {
                int idx = tid + i * 256;
                int row = idx >> 3, f4 = idx & 7;
                *(uint2*)(dA + row * PITCHB + f4 * 8) = sa[i];
            }
#pragma unroll
            for (int i = 0; i < 2; i++) {
                int idx = tid + i * 256;
                int row = idx >> 2, q = idx & 3;
                *(uint4*)(dB + row * PITCHB + q * 16) = sb[i];
            }
        }
        __syncthreads();
    }

    // ---- epilogue: write fp32 result
#pragma unroll
    for (int mt = 0; mt < 2; mt++) {
        int r0 = bm0 + warp_m * 32 + mt * 16 + gid;
        int r1 = r0 + 8;
#pragma unroll
        for (int nt = 0; nt < 8; nt++) {
            int col = bn0 + warp_n * 64 + nt * 8 + tg * 2;
            if (r0 < M)
                *(float2*)(d_xw1 + (size_t)r0 * F1 + col) =
                    make_float2(acc[mt][nt][0], acc[mt][nt][1]);
            if (r1 < M)
                *(float2*)(d_xw1 + (size_t)r1 * F1 + col) =
                    make_float2(acc[mt][nt][2], acc[mt][nt][3]);
        }
    }
}

// ---------------------------------------------------------------------------
// SpMM1: h = relu(A_sparse @ xw1), warp-per-row
// ---------------------------------------------------------------------------
__global__ void spmm1_kernel(int Nn) {
    int warp = (blockIdx.x * blockDim.x + threadIdx.x) >> 5;
    int lane = threadIdx.x & 31;
    if (warp >= Nn) return;
    int s = d_rowptr[warp], e = d_rowptr[warp + 1];
    float4 a0 = make_float4(0.f, 0.f, 0.f, 0.f);
    float4 a1 = make_float4(0.f, 0.f, 0.f, 0.f);
    for (int i = s; i < e; i++) {
        int c = __ldg(&d_cols[i]);
        float v = __ldg(&d_vals[i]);
        const float4* p = (const float4*)(d_xw1 + (size_t)c * F1);
        float4 x0 = __ldg(&p[lane]);
        float4 x1 = __ldg(&p[lane + 32]);
        a0.x = fmaf(v, x0.x, a0.x); a0.y = fmaf(v, x0.y, a0.y);
        a0.z = fmaf(v, x0.z, a0.z); a0.w = fmaf(v, x0.w, a0.w);
        a1.x = fmaf(v, x1.x, a1.x); a1.y = fmaf(v, x1.y, a1.y);
        a1.z = fmaf(v, x1.z, a1.z); a1.w = fmaf(v, x1.w, a1.w);
    }
    float4* o = (float4*)(d_h + (size_t)warp * F1);
    o[lane]      = make_float4(fmaxf(a0.x, 0.f), fmaxf(a0.y, 0.f),
                               fmaxf(a0.z, 0.f), fmaxf(a0.w, 0.f));
    o[lane + 32] = make_float4(fmaxf(a1.x, 0.f), fmaxf(a1.y, 0.f),
                               fmaxf(a1.z, 0.f), fmaxf(a1.w, 0.f));
}

// ---------------------------------------------------------------------------
// BN stats / finalize
// ---------------------------------------------------------------------------
__global__ void bnstats_kernel(const float* __restrict__ h, float* __restrict__ sum,
                               float* __restrict__ sumsq, int Nn, int F) {
    int col = threadIdx.x;
    float s = 0.f, s2 = 0.f;
    for (int r = blockIdx.x; r < Nn; r += gridDim.x) {
        float v = h[(size_t)r * F + col];
        s += v;
        s2 = fmaf(v, v, s2);
    }
    atomicAdd(&sum[col], s);
    atomicAdd(&sumsq[col], s2);
}

__global__ void bnfin_kernel(const float* __restrict__ sum, const float* __restrict__ sumsq,
                             const float* __restrict__ gamma, const float* __restrict__ beta,
                             float* __restrict__ scale, float* __restrict__ bias,
                             int Nn, int F) {
    int c = threadIdx.x;
    if (c >= F) return;
    float inv = 1.f / (float)Nn;
    float mean = sum[c] * inv;
    float var = sumsq[c] * inv - mean * mean;
    float rs = rsqrtf(var + 1e-5f);
    float sc = gamma[c] * rs;
    scale[c] = sc;
    bias[c] = beta[c] - mean * sc;
}

// ---------------------------------------------------------------------------
// GEMM2: hw2 = relu(bn1(h)) @ W2   (BN1+ReLU fused into A load)
// ---------------------------------------------------------------------------
__global__ void gemm2_kernel(const float* __restrict__ B, int M) {
    __shared__ float As[16][128];
    __shared__ float Bs[16][64];
    __shared__ float s_sc[F1], s_bi[F1];
    const int tid = threadIdx.x;
    s_sc[tid] = d_scale1[tid];
    s_bi[tid] = d_bias1[tid];
    const int bm0 = blockIdx.x * 128;
    const int tx = tid & 15, ty = tid >> 4;
    const int ar = tid >> 2, ac = (tid & 3) * 4;
    const int br = tid >> 4, bc = (tid & 15) * 4;

    float acc[8][4];
#pragma unroll
    for (int i = 0; i < 8; i++)
#pragma unroll
        for (int j = 0; j < 4; j++) acc[i][j] = 0.f;
    __syncthreads();

    for (int k0 = 0; k0 < F1; k0 += 16) {
#pragma unroll
        for (int h = 0; h < 2; h++) {
            int row = bm0 + ar + h * 64;
            float4 a = make_float4(0.f, 0.f, 0.f, 0.f);
            if (row < M) {
                a = *(const float4*)(d_h + (size_t)row * F1 + k0 + ac);
                a.x = fmaxf(fmaf(a.x, s_sc[k0 + ac + 0], s_bi[k0 + ac + 0]), 0.f);
                a.y = fmaxf(fmaf(a.y, s_sc[k0 + ac + 1], s_bi[k0 + ac + 1]), 0.f);
                a.z = fmaxf(fmaf(a.z, s_sc[k0 + ac + 2], s_bi[k0 + ac + 2]), 0.f);
                a.w = fmaxf(fmaf(a.w, s_sc[k0 + ac + 3], s_bi[k0 + ac + 3]), 0.f);
            }
            As[ac + 0][ar + h * 64] = a.x;
            As[ac + 1][ar + h * 64] = a.y;
            As[ac + 2][ar + h * 64] = a.z;
            As[ac + 3][ar + h * 64] = a.w;
        }
        float4 b = *(const float4*)(B + (size_t)(k0 + br) * F2 + bc);
        *(float4*)&Bs[br][bc] = b;
        __syncthreads();
#pragma unroll
        for (int k = 0; k < 16; k++) {
            float areg[8];
            float4 breg = *(float4*)&Bs[k][tx * 4];
#pragma unroll
            for (int i = 0; i < 8; i++) areg[i] = As[k][ty + i * 16];
#pragma unroll
            for (int i = 0; i < 8; i++) {
                acc[i][0] = fmaf(areg[i], breg.x, acc[i][0]);
                acc[i][1] = fmaf(areg[i], breg.y, acc[i][1]);
                acc[i][2] = fmaf(areg[i], breg.z, acc[i][2]);
                acc[i][3] = fmaf(areg[i], breg.w, acc[i][3]);
            }
        }
        __syncthreads();
    }
#pragma unroll
    for (int i = 0; i < 8; i++) {
        int row = bm0 + ty + i * 16;
        if (row < M) {
            float4 v = make_float4(acc[i][0], acc[i][1], acc[i][2], acc[i][3]);
            *(float4*)(d_hw2 + (size_t)row * F2 + tx * 4) = v;
        }
    }
}

// ---------------------------------------------------------------------------
// SpMM2: out = relu(A_sparse @ hw2)
// ---------------------------------------------------------------------------
__global__ void spmm2_kernel(float* __restrict__ out, int Nn) {
    int warp = (blockIdx.x * blockDim.x + threadIdx.x) >> 5;
    int lane = threadIdx.x & 31;
    if (warp >= Nn) return;
    int s = d_rowptr[warp], e = d_rowptr[warp + 1];
    float2 acc = make_float2(0.f, 0.f);
    for (int i = s; i < e; i++) {
        int c = __ldg(&d_cols[i]);
        float v = __ldg(&d_vals[i]);
        const float2* p = (const float2*)(d_hw2 + (size_t)c * F2);
        float2 x0 = __ldg(&p[lane]);
        acc.x = fmaf(v, x0.x, acc.x);
        acc.y = fmaf(v, x0.y, acc.y);
    }
    float2* o = (float2*)(out + (size_t)warp * F2);
    o[lane] = make_float2(fmaxf(acc.x, 0.f), fmaxf(acc.y, 0.f));
}

// ---------------------------------------------------------------------------
// BN2 apply in place on d_out
// ---------------------------------------------------------------------------
__global__ void bnapply2_kernel(float* __restrict__ out, int total) {
    int i = blockIdx.x * blockDim.x + threadIdx.x;
    if (i < total) {
        int c = i & (F2 - 1);
        out[i] = fmaf(out[i], d_scale2[c], d_bias2[c]);
    }
}

// ---------------------------------------------------------------------------
// Launch sequence
// ---------------------------------------------------------------------------
extern "C" void kernel_launch(void* const* d_in, const int* in_sizes, int n_in,
                              void* d_out, int out_size) {
    const float* x    = (const float*)d_in[0];
    const int*   erow = (const int*)d_in[1];
    const int*   ecol = (const int*)d_in[2];
    const float* evl  = (const float*)d_in[3];
    const float* W1   = (const float*)d_in[4];
    const float* g1   = (const float*)d_in[5];
    const float* b1   = (const float*)d_in[6];
    const float* W2   = (const float*)d_in[7];
    const float* g2   = (const float*)d_in[8];
    const float* b2   = (const float*)d_in[9];
    float* out = (float*)d_out;

    const int Nn = in_sizes[0] / F0;   // 100000
    const int E  = in_sizes[1];        // 3200000
    const int nch = (Nn + 1023) / 1024;

    float* p_sum1   = nullptr; cudaGetSymbolAddress((void**)&p_sum1,   d_sum1);
    float* p_sumsq1 = nullptr; cudaGetSymbolAddress((void**)&p_sumsq1, d_sumsq1);
    float* p_scale1 = nullptr; cudaGetSymbolAddress((void**)&p_scale1, d_scale1);
    float* p_bias1  = nullptr; cudaGetSymbolAddress((void**)&p_bias1,  d_bias1);
    float* p_sum2   = nullptr; cudaGetSymbolAddress((void**)&p_sum2,   d_sum2);
    float* p_sumsq2 = nullptr; cudaGetSymbolAddress((void**)&p_sumsq2, d_sumsq2);
    float* p_scale2 = nullptr; cudaGetSymbolAddress((void**)&p_scale2, d_scale2);
    float* p_bias2  = nullptr; cudaGetSymbolAddress((void**)&p_bias2,  d_bias2);
    float* p_h      = nullptr; cudaGetSymbolAddress((void**)&p_h,      d_h);

    // Weight split for GEMM1
    prepW1_kernel<<<(F0 * F1 + 255) / 256, 256>>>(W1);

    // CSR build
    zero_kernel<<<(Nn + 255) / 256, 256>>>(Nn);
    hist_kernel<<<(E + 255) / 256, 256>>>(erow, E);
    scanA_kernel<<<nch, 1024>>>(Nn);
    scanB_kernel<<<1, 128>>>(nch);
    scanC_kernel<<<(Nn + 255) / 256, 256>>>(Nn, E);
    scatter_kernel<<<(E + 255) / 256, 256>>>(erow, ecol, evl, E);

    // Layer 1 (tensor-core GEMM1 via mma.sync)
    gemm1_mma_kernel<<<dim3((Nn + 127) / 128, 2), 256>>>(x, Nn);
    spmm1_kernel<<<(Nn + 7) / 8, 256>>>(Nn);
    bnstats_kernel<<<784, F1>>>(p_h, p_sum1, p_sumsq1, Nn, F1);
    bnfin_kernel<<<1, F1>>>(p_sum1, p_sumsq1, g1, b1, p_scale1, p_bias1, Nn, F1);

    // Layer 2
    gemm2_kernel<<<dim3((Nn + 127) / 128, 1), 256>>>(W2, Nn);
    spmm2_kernel<<<(Nn + 7) / 8, 256>>>(out, Nn);
    bnstats_kernel<<<784, F2>>>(out, p_sum2, p_sumsq2, Nn, F2);
    bnfin_kernel<<<1, F2>>>(p_sum2, p_sumsq2, g2, b2, p_scale2, p_bias2, Nn, F2);
    bnapply2_kernel<<<(Nn * F2 + 255) / 256, 256>>>(out, Nn * F2);
}

// round 5
// speedup vs baseline: 1.9416x; 1.4080x over previous
#include <cuda_runtime.h>
#include <cuda_bf16.h>
#include <cuda_fp16.h>
#include <stdint.h>

// ---------------------------------------------------------------------------
// Problem constants
// ---------------------------------------------------------------------------
#define NMAX 100000
#define EMAX 3200000
#define F0 512
#define F1 256
#define F2 64

// ---------------------------------------------------------------------------
// Static device scratch
// ---------------------------------------------------------------------------
__device__ float d_xw1[NMAX * F1];
__device__ float d_h[NMAX * F1];
__device__ float d_hw2[NMAX * F2];
__device__ int   d_cnt[NMAX];
__device__ int   d_fill[NMAX];
__device__ int   d_rowptr[NMAX + 1];
__device__ int   d_cols[EMAX];
__device__ float d_vals[EMAX];
__device__ int   d_chunksums[128];
__device__ float d_sum1[F1], d_sumsq1[F1], d_scale1[F1], d_bias1[F1];
__device__ float d_sum2[F2], d_sumsq2[F2], d_scale2[F2], d_bias2[F2];
// W1_hi as fp16, layout [N=256][K=512] K-major
__device__ __align__(128) __half d_Bh[F1 * F0];
// W2_hi as fp16, layout [N=64][K=256] K-major
__device__ __align__(128) __half d_B2h[F2 * F1];

// ---------------------------------------------------------------------------
// Helpers
// ---------------------------------------------------------------------------
__device__ __forceinline__ uint32_t smem_u32(const void* p) {
    uint32_t a;
    asm("{ .reg .u64 t; cvta.to.shared.u64 t, %1; cvt.u32.u64 %0, t; }" : "=r"(a) : "l"(p));
    return a;
}
__device__ __forceinline__ uint32_t pack2hi_h(float a, float b) {
    __half2 t = __floats2half2_rn(a, b);
    return *(uint32_t*)&t;
}
__device__ __forceinline__ uint32_t pack2lo_h(float a, float b) {
    float ah = __half2float(__float2half_rn(a));
    float bh = __half2float(__float2half_rn(b));
    __half2 t = __floats2half2_rn(a - ah, b - bh);
    return *(uint32_t*)&t;
}
__device__ __forceinline__ void mma_f16(float* d, const uint32_t* a, uint32_t b0, uint32_t b1) {
    asm volatile(
        "mma.sync.aligned.m16n8k16.row.col.f32.f16.f16.f32 "
        "{%0,%1,%2,%3}, {%4,%5,%6,%7}, {%8,%9}, {%0,%1,%2,%3};"
        : "+f"(d[0]), "+f"(d[1]), "+f"(d[2]), "+f"(d[3])
        : "r"(a[0]), "r"(a[1]), "r"(a[2]), "r"(a[3]), "r"(b0), "r"(b1));
}
__device__ __forceinline__ void ldmatrix_x4(uint32_t* r, uint32_t addr) {
    asm volatile("ldmatrix.sync.aligned.m8n8.x4.shared.b16 {%0,%1,%2,%3}, [%4];"
                 : "=r"(r[0]), "=r"(r[1]), "=r"(r[2]), "=r"(r[3]) : "r"(addr));
}
__device__ __forceinline__ void cp_async16(uint32_t saddr, const void* gptr) {
    asm volatile("cp.async.ca.shared.global [%0], [%1], 16;" :: "r"(saddr), "l"(gptr));
}
__device__ __forceinline__ void cp_commit() {
    asm volatile("cp.async.commit_group;" ::: "memory");
}
__device__ __forceinline__ void cp_wait0() {
    asm volatile("cp.async.wait_group 0;" ::: "memory");
}

// ---------------------------------------------------------------------------
// Zero transient accumulators
// ---------------------------------------------------------------------------
__global__ void zero_kernel(int Nn) {
    int i = blockIdx.x * blockDim.x + threadIdx.x;
    if (i < Nn) { d_cnt[i] = 0; d_fill[i] = 0; }
    if (i < F1) { d_sum1[i] = 0.f; d_sumsq1[i] = 0.f; }
    if (i < F2) { d_sum2[i] = 0.f; d_sumsq2[i] = 0.f; }
}

// ---------------------------------------------------------------------------
// CSR build
// ---------------------------------------------------------------------------
__global__ void hist_kernel(const int* __restrict__ erow, int E) {
    int i = blockIdx.x * blockDim.x + threadIdx.x;
    if (i < E) atomicAdd(&d_cnt[erow[i]], 1);
}

__global__ void scanA_kernel(int Nn) {
    __shared__ int sh[1024];
    int gid = blockIdx.x * 1024 + threadIdx.x;
    int v = (gid < Nn) ? d_cnt[gid] : 0;
    sh[threadIdx.x] = v;
    __syncthreads();
#pragma unroll
    for (int off = 1; off < 1024; off <<= 1) {
        int t = (threadIdx.x >= off) ? sh[threadIdx.x - off] : 0;
        __syncthreads();
        sh[threadIdx.x] += t;
        __syncthreads();
    }
    if (gid < Nn) d_rowptr[gid] = sh[threadIdx.x] - v;
    if (threadIdx.x == 1023) d_chunksums[blockIdx.x] = sh[1023];
}

__global__ void scanB_kernel(int nch) {
    __shared__ int sh[128];
    int v = (threadIdx.x < nch) ? d_chunksums[threadIdx.x] : 0;
    sh[threadIdx.x] = v;
    __syncthreads();
#pragma unroll
    for (int off = 1; off < 128; off <<= 1) {
        int t = (threadIdx.x >= off) ? sh[threadIdx.x - off] : 0;
        __syncthreads();
        sh[threadIdx.x] += t;
        __syncthreads();
    }
    if (threadIdx.x < nch) d_chunksums[threadIdx.x] = sh[threadIdx.x] - v;
}

__global__ void scanC_kernel(int Nn, int E) {
    int gid = blockIdx.x * blockDim.x + threadIdx.x;
    if (gid < Nn) d_rowptr[gid] += d_chunksums[gid >> 10];
    if (gid == 0) d_rowptr[Nn] = E;
}

__global__ void scatter_kernel(const int* __restrict__ erow,
                               const int* __restrict__ ecol,
                               const float* __restrict__ eval, int E) {
    int i = blockIdx.x * blockDim.x + threadIdx.x;
    if (i < E) {
        int r = erow[i];
        int p = d_rowptr[r] + atomicAdd(&d_fill[r], 1);
        d_cols[p] = ecol[i];
        d_vals[p] = eval[i];
    }
}

// ---------------------------------------------------------------------------
// Weight prep: W_hi = fp16(W), transposed to K-major
// ---------------------------------------------------------------------------
__global__ void prepW1_kernel(const float* __restrict__ W1) {
    int i = blockIdx.x * blockDim.x + threadIdx.x;
    if (i >= F0 * F1) return;
    int k = i >> 8;        // 0..511
    int n = i & 255;       // 0..255
    d_Bh[(size_t)n * F0 + k] = __float2half_rn(W1[i]);
}
__global__ void prepW2_kernel(const float* __restrict__ W2) {
    int i = blockIdx.x * blockDim.x + threadIdx.x;
    if (i >= F1 * F2) return;
    int k = i >> 6;        // 0..255
    int n = i & 63;        // 0..63
    d_B2h[(size_t)n * F1 + k] = __float2half_rn(W2[i]);
}

// ---------------------------------------------------------------------------
// GEMM1 via mma.sync fp16 2-term: xw1 = x @ W1  (= A_hi*B_hi + A_lo*B_hi)
// Block tile 128x128; warp tile 32x64 (4x2 warps); 16 k-blocks of 32 fp32 cols.
// Per k-block: x read once -> packed into A_hi and A_lo SMEM tiles; B via cp.async.
// SMEM pitch 80B, double-buffered.
// ---------------------------------------------------------------------------
#define PITCHB 80
#define BUFS1 30720          // A_hi 10240 | A_lo 10240 | B 10240
#define SMEM1 (2 * BUFS1)
#define KBLK1 16

__global__ void __launch_bounds__(256, 2)
gemm1_mma_kernel(const float* __restrict__ x, int M) {
    extern __shared__ __align__(16) char sm[];
    const int tid = threadIdx.x;
    const int wid = tid >> 5;
    const int lane = tid & 31;
    const int warp_m = wid & 3;
    const int warp_n = wid >> 2;
    const int gid = lane >> 2;
    const int tg = lane & 3;
    const int bm0 = blockIdx.x * 128;
    const int bn0 = blockIdx.y * 128;
    const uint32_t sb = smem_u32(sm);

    float acc[2][8][4];
#pragma unroll
    for (int mt = 0; mt < 2; mt++)
#pragma unroll
        for (int nt = 0; nt < 8; nt++)
#pragma unroll
            for (int q = 0; q < 4; q++) acc[mt][nt][q] = 0.f;

    const int arow = tid >> 3;          // A-pack: thread -> (row, float4 idx)
    const int af4 = tid & 7;
    const int brow = tid >> 2;          // B cp.async: thread -> (row, 16B idx)
    const int bq = tid & 3;

    // ---- prologue: k-block 0
    {
#pragma unroll
        for (int i = 0; i < 4; i++) {
            int row = arow + i * 32;
            int rg = bm0 + row;
            float4 f = make_float4(0.f, 0.f, 0.f, 0.f);
            if (rg < M) f = *(const float4*)(x + (size_t)rg * F0 + af4 * 4);
            *(uint2*)(sm + row * PITCHB + af4 * 8) =
                make_uint2(pack2hi_h(f.x, f.y), pack2hi_h(f.z, f.w));
            *(uint2*)(sm + 10240 + row * PITCHB + af4 * 8) =
                make_uint2(pack2lo_h(f.x, f.y), pack2lo_h(f.z, f.w));
        }
#pragma unroll
        for (int i = 0; i < 2; i++) {
            int row = brow + i * 64;
            cp_async16(sb + 20480 + row * PITCHB + bq * 16,
                       d_Bh + (size_t)(bn0 + row) * F0 + bq * 8);
        }
        cp_commit();
        cp_wait0();
        __syncthreads();
    }

    for (int c = 0; c < KBLK1; c++) {
        const int buf = c & 1;
        float4 fa[4];
        const bool have = (c + 1 < KBLK1);
        if (have) {
            const int sk0 = (c + 1) * 32;
#pragma unroll
            for (int i = 0; i < 4; i++) {
                int row = arow + i * 32;
                int rg = bm0 + row;
                fa[i] = make_float4(0.f, 0.f, 0.f, 0.f);
                if (rg < M) fa[i] = *(const float4*)(x + (size_t)rg * F0 + sk0 + af4 * 4);
            }
            const uint32_t bdst = sb + (buf ^ 1) * BUFS1 + 20480;
#pragma unroll
            for (int i = 0; i < 2; i++) {
                int row = brow + i * 64;
                cp_async16(bdst + row * PITCHB + bq * 16,
                           d_Bh + (size_t)(bn0 + row) * F0 + sk0 + bq * 8);
            }
            cp_commit();
        }
        // ---- compute on buf
        const uint32_t sA = sb + buf * BUFS1;
        const char* Bb = sm + buf * BUFS1 + 20480;
#pragma unroll
        for (int ks = 0; ks < 2; ks++) {
#pragma unroll
            for (int pass = 0; pass < 2; pass++) {
                uint32_t afrag[2][4];
                const uint32_t base = sA + pass * 10240;
#pragma unroll
                for (int mt = 0; mt < 2; mt++) {
                    uint32_t addr = base + (warp_m * 32 + mt * 16 + (lane & 15)) * PITCHB
                                    + ks * 32 + (lane >> 4) * 16;
                    ldmatrix_x4(afrag[mt], addr);
                }
#pragma unroll
                for (int nt = 0; nt < 8; nt++) {
                    const char* bp = Bb + (warp_n * 64 + nt * 8 + gid) * PITCHB
                                     + ks * 32 + tg * 4;
                    uint32_t b0 = *(const uint32_t*)bp;
                    uint32_t b1 = *(const uint32_t*)(bp + 16);
                    mma_f16(acc[0][nt], afrag[0], b0, b1);
                    mma_f16(acc[1][nt], afrag[1], b0, b1);
                }
            }
        }
        // ---- commit staged A to the other buffer
        if (have) {
            char* dA = sm + (buf ^ 1) * BUFS1;
#pragma unroll
            for (int i = 0; i < 4; i++) {
                int row = arow + i * 32;
                *(uint2*)(dA + row * PITCHB + af4 * 8) =
                    make_uint2(pack2hi_h(fa[i].x, fa[i].y), pack2hi_h(fa[i].z, fa[i].w));
                *(uint2*)(dA + 10240 + row * PITCHB + af4 * 8) =
                    make_uint2(pack2lo_h(fa[i].x, fa[i].y), pack2lo_h(fa[i].z, fa[i].w));
            }
        }
        cp_wait0();
        __syncthreads();
    }

    // ---- epilogue
#pragma unroll
    for (int mt = 0; mt < 2; mt++) {
        int r0 = bm0 + warp_m * 32 + mt * 16 + gid;
        int r1 = r0 + 8;
#pragma unroll
        for (int nt = 0; nt < 8; nt++) {
            int col = bn0 + warp_n * 64 + nt * 8 + tg * 2;
            if (r0 < M)
                *(float2*)(d_xw1 + (size_t)r0 * F1 + col) =
                    make_float2(acc[mt][nt][0], acc[mt][nt][1]);
            if (r1 < M)
                *(float2*)(d_xw1 + (size_t)r1 * F1 + col) =
                    make_float2(acc[mt][nt][2], acc[mt][nt][3]);
        }
    }
}

// ---------------------------------------------------------------------------
// GEMM2 via mma.sync fp16 2-term: hw2 = relu(bn1(h)) @ W2
// Block tile 128x64; 8 warps, warp tile 16x64; 8 k-blocks of 32 fp32 cols.
// BN1 affine + ReLU fused into the A pack.
// ---------------------------------------------------------------------------
#define BUFS2 25600          // A_hi 10240 | A_lo 10240 | B 5120
#define SMEM2 (2 * BUFS2)
#define KBLK2 8

__global__ void __launch_bounds__(256, 2)
gemm2_mma_kernel(const float* __restrict__ W2unused, int M) {
    extern __shared__ __align__(16) char sm[];
    __shared__ float s_sc[F1], s_bi[F1];
    const int tid = threadIdx.x;
    const int wid = tid >> 5;
    const int lane = tid & 31;
    const int gid = lane >> 2;
    const int tg = lane & 3;
    const int bm0 = blockIdx.x * 128;
    const uint32_t sb = smem_u32(sm);

    s_sc[tid] = d_scale1[tid];
    s_bi[tid] = d_bias1[tid];
    __syncthreads();

    float acc[8][4];
#pragma unroll
    for (int nt = 0; nt < 8; nt++)
#pragma unroll
        for (int q = 0; q < 4; q++) acc[nt][q] = 0.f;

    const int arow = tid >> 3;
    const int af4 = tid & 7;
    const int brow = tid >> 2;   // 0..63
    const int bq = tid & 3;

    // A pack with BN1+ReLU fusion
    auto packA = [&](char* dst, int sk0) {
#pragma unroll
        for (int i = 0; i < 4; i++) {
            int row = arow + i * 32;
            int rg = bm0 + row;
            float4 f = make_float4(0.f, 0.f, 0.f, 0.f);
            if (rg < M) {
                f = *(const float4*)(d_h + (size_t)rg * F1 + sk0 + af4 * 4);
                int cb = sk0 + af4 * 4;
                f.x = fmaxf(fmaf(f.x, s_sc[cb + 0], s_bi[cb + 0]), 0.f);
                f.y = fmaxf(fmaf(f.y, s_sc[cb + 1], s_bi[cb + 1]), 0.f);
                f.z = fmaxf(fmaf(f.z, s_sc[cb + 2], s_bi[cb + 2]), 0.f);
                f.w = fmaxf(fmaf(f.w, s_sc[cb + 3], s_bi[cb + 3]), 0.f);
            }
            *(uint2*)(dst + row * PITCHB + af4 * 8) =
                make_uint2(pack2hi_h(f.x, f.y), pack2hi_h(f.z, f.w));
            *(uint2*)(dst + 10240 + row * PITCHB + af4 * 8) =
                make_uint2(pack2lo_h(f.x, f.y), pack2lo_h(f.z, f.w));
        }
    };

    // ---- prologue: k-block 0
    packA(sm, 0);
    cp_async16(sb + 20480 + brow * PITCHB + bq * 16,
               d_B2h + (size_t)brow * F1 + bq * 8);
    cp_commit();
    cp_wait0();
    __syncthreads();

    for (int c = 0; c < KBLK2; c++) {
        const int buf = c & 1;
        const bool have = (c + 1 < KBLK2);
        if (have) {
            const int sk0 = (c + 1) * 32;
            cp_async16(sb + (buf ^ 1) * BUFS2 + 20480 + brow * PITCHB + bq * 16,
                       d_B2h + (size_t)brow * F1 + sk0 + bq * 8);
            cp_commit();
        }
        // compute on buf
        const uint32_t sA = sb + buf * BUFS2;
        const char* Bb = sm + buf * BUFS2 + 20480;
#pragma unroll
        for (int ks = 0; ks < 2; ks++) {
#pragma unroll
            for (int pass = 0; pass < 2; pass++) {
                uint32_t afrag[4];
                uint32_t addr = sA + pass * 10240
                                + (wid * 16 + (lane & 15)) * PITCHB
                                + ks * 32 + (lane >> 4) * 16;
                ldmatrix_x4(afrag, addr);
#pragma unroll
                for (int nt = 0; nt < 8; nt++) {
                    const char* bp = Bb + (nt * 8 + gid) * PITCHB + ks * 32 + tg * 4;
                    uint32_t b0 = *(const uint32_t*)bp;
                    uint32_t b1 = *(const uint32_t*)(bp + 16);
                    mma_f16(acc[nt], afrag, b0, b1);
                }
            }
        }
        if (have) packA(sm + (buf ^ 1) * BUFS2, (c + 1) * 32);
        cp_wait0();
        __syncthreads();
    }

    // ---- epilogue
    int r0 = bm0 + wid * 16 + gid;
    int r1 = r0 + 8;
#pragma unroll
    for (int nt = 0; nt < 8; nt++) {
        int col = nt * 8 + tg * 2;
        if (r0 < M)
            *(float2*)(d_hw2 + (size_t)r0 * F2 + col) = make_float2(acc[nt][0], acc[nt][1]);
        if (r1 < M)
            *(float2*)(d_hw2 + (size_t)r1 * F2 + col) = make_float2(acc[nt][2], acc[nt][3]);
    }
}

// ---------------------------------------------------------------------------
// SpMM1: h = relu(A_sparse @ xw1), warp-per-row
// ---------------------------------------------------------------------------
__global__ void spmm1_kernel(int Nn) {
    int warp = (blockIdx.x * blockDim.x + threadIdx.x) >> 5;
    int lane = threadIdx.x & 31;
    if (warp >= Nn) return;
    int s = d_rowptr[warp], e = d_rowptr[warp + 1];
    float4 a0 = make_float4(0.f, 0.f, 0.f, 0.f);
    float4 a1 = make_float4(0.f, 0.f, 0.f, 0.f);
#pragma unroll 2
    for (int i = s; i < e; i++) {
        int c = __ldg(&d_cols[i]);
        float v = __ldg(&d_vals[i]);
        const float4* p = (const float4*)(d_xw1 + (size_t)c * F1);
        float4 x0 = __ldg(&p[lane]);
        float4 x1 = __ldg(&p[lane + 32]);
        a0.x = fmaf(v, x0.x, a0.x); a0.y = fmaf(v, x0.y, a0.y);
        a0.z = fmaf(v, x0.z, a0.z); a0.w = fmaf(v, x0.w, a0.w);
        a1.x = fmaf(v, x1.x, a1.x); a1.y = fmaf(v, x1.y, a1.y);
        a1.z = fmaf(v, x1.z, a1.z); a1.w = fmaf(v, x1.w, a1.w);
    }
    float4* o = (float4*)(d_h + (size_t)warp * F1);
    o[lane]      = make_float4(fmaxf(a0.x, 0.f), fmaxf(a0.y, 0.f),
                               fmaxf(a0.z, 0.f), fmaxf(a0.w, 0.f));
    o[lane + 32] = make_float4(fmaxf(a1.x, 0.f), fmaxf(a1.y, 0.f),
                               fmaxf(a1.z, 0.f), fmaxf(a1.w, 0.f));
}

// ---------------------------------------------------------------------------
// BN stats / finalize
// ---------------------------------------------------------------------------
__global__ void bnstats_kernel(const float* __restrict__ h, float* __restrict__ sum,
                               float* __restrict__ sumsq, int Nn, int F) {
    int col = threadIdx.x;
    float s = 0.f, s2 = 0.f;
    for (int r = blockIdx.x; r < Nn; r += gridDim.x) {
        float v = h[(size_t)r * F + col];
        s += v;
        s2 = fmaf(v, v, s2);
    }
    atomicAdd(&sum[col], s);
    atomicAdd(&sumsq[col], s2);
}

__global__ void bnfin_kernel(const float* __restrict__ sum, const float* __restrict__ sumsq,
                             const float* __restrict__ gamma, const float* __restrict__ beta,
                             float* __restrict__ scale, float* __restrict__ bias,
                             int Nn, int F) {
    int c = threadIdx.x;
    if (c >= F) return;
    float inv = 1.f / (float)Nn;
    float mean = sum[c] * inv;
    float var = sumsq[c] * inv - mean * mean;
    float rs = rsqrtf(var + 1e-5f);
    float sc = gamma[c] * rs;
    scale[c] = sc;
    bias[c] = beta[c] - mean * sc;
}

// ---------------------------------------------------------------------------
// SpMM2: out = relu(A_sparse @ hw2)
// ---------------------------------------------------------------------------
__global__ void spmm2_kernel(float* __restrict__ out, int Nn) {
    int warp = (blockIdx.x * blockDim.x + threadIdx.x) >> 5;
    int lane = threadIdx.x & 31;
    if (warp >= Nn) return;
    int s = d_rowptr[warp], e = d_rowptr[warp + 1];
    float2 acc = make_float2(0.f, 0.f);
#pragma unroll 2
    for (int i = s; i < e; i++) {
        int c = __ldg(&d_cols[i]);
        float v = __ldg(&d_vals[i]);
        const float2* p = (const float2*)(d_hw2 + (size_t)c * F2);
        float2 x0 = __ldg(&p[lane]);
        acc.x = fmaf(v, x0.x, acc.x);
        acc.y = fmaf(v, x0.y, acc.y);
    }
    float2* o = (float2*)(out + (size_t)warp * F2);
    o[lane] = make_float2(fmaxf(acc.x, 0.f), fmaxf(acc.y, 0.f));
}

// ---------------------------------------------------------------------------
// BN2 apply in place on d_out
// ---------------------------------------------------------------------------
__global__ void bnapply2_kernel(float* __restrict__ out, int total) {
    int i = blockIdx.x * blockDim.x + threadIdx.x;
    if (i < total) {
        int c = i & (F2 - 1);
        out[i] = fmaf(out[i], d_scale2[c], d_bias2[c]);
    }
}

// ---------------------------------------------------------------------------
// Launch sequence
// ---------------------------------------------------------------------------
extern "C" void kernel_launch(void* const* d_in, const int* in_sizes, int n_in,
                              void* d_out, int out_size) {
    const float* x    = (const float*)d_in[0];
    const int*   erow = (const int*)d_in[1];
    const int*   ecol = (const int*)d_in[2];
    const float* evl  = (const float*)d_in[3];
    const float* W1   = (const float*)d_in[4];
    const float* g1   = (const float*)d_in[5];
    const float* b1   = (const float*)d_in[6];
    const float* W2   = (const float*)d_in[7];
    const float* g2   = (const float*)d_in[8];
    const float* b2   = (const float*)d_in[9];
    float* out = (float*)d_out;

    const int Nn = in_sizes[0] / F0;   // 100000
    const int E  = in_sizes[1];        // 3200000
    const int nch = (Nn + 1023) / 1024;

    float* p_sum1   = nullptr; cudaGetSymbolAddress((void**)&p_sum1,   d_sum1);
    float* p_sumsq1 = nullptr; cudaGetSymbolAddress((void**)&p_sumsq1, d_sumsq1);
    float* p_scale1 = nullptr; cudaGetSymbolAddress((void**)&p_scale1, d_scale1);
    float* p_bias1  = nullptr; cudaGetSymbolAddress((void**)&p_bias1,  d_bias1);
    float* p_sum2   = nullptr; cudaGetSymbolAddress((void**)&p_sum2,   d_sum2);
    float* p_sumsq2 = nullptr; cudaGetSymbolAddress((void**)&p_sumsq2, d_sumsq2);
    float* p_scale2 = nullptr; cudaGetSymbolAddress((void**)&p_scale2, d_scale2);
    float* p_bias2  = nullptr; cudaGetSymbolAddress((void**)&p_bias2,  d_bias2);
    float* p_h      = nullptr; cudaGetSymbolAddress((void**)&p_h,      d_h);

    static int attr_done = 0;
    if (!attr_done) {
        cudaFuncSetAttribute(gemm1_mma_kernel,
                             cudaFuncAttributeMaxDynamicSharedMemorySize, SMEM1);
        cudaFuncSetAttribute(gemm2_mma_kernel,
                             cudaFuncAttributeMaxDynamicSharedMemorySize, SMEM2);
        attr_done = 1;
    }

    // Weight prep
    prepW1_kernel<<<(F0 * F1 + 255) / 256, 256>>>(W1);
    prepW2_kernel<<<(F1 * F2 + 255) / 256, 256>>>(W2);

    // CSR build
    zero_kernel<<<(Nn + 255) / 256, 256>>>(Nn);
    hist_kernel<<<(E + 255) / 256, 256>>>(erow, E);
    scanA_kernel<<<nch, 1024>>>(Nn);
    scanB_kernel<<<1, 128>>>(nch);
    scanC_kernel<<<(Nn + 255) / 256, 256>>>(Nn, E);
    scatter_kernel<<<(E + 255) / 256, 256>>>(erow, ecol, evl, E);

    // Layer 1
    gemm1_mma_kernel<<<dim3((Nn + 127) / 128, 2), 256, SMEM1>>>(x, Nn);
    spmm1_kernel<<<(Nn + 7) / 8, 256>>>(Nn);
    bnstats_kernel<<<784, F1>>>(p_h, p_sum1, p_sumsq1, Nn, F1);
    bnfin_kernel<<<1, F1>>>(p_sum1, p_sumsq1, g1, b1, p_scale1, p_bias1, Nn, F1);

    // Layer 2
    gemm2_mma_kernel<<<(Nn + 127) / 128, 256, SMEM2>>>(nullptr, Nn);
    spmm2_kernel<<<(Nn + 7) / 8, 256>>>(out, Nn);
    bnstats_kernel<<<784, F2>>>(out, p_sum2, p_sumsq2, Nn, F2);
    bnfin_kernel<<<1, F2>>>(p_sum2, p_sumsq2, g2, b2, p_scale2, p_bias2, Nn, F2);
    bnapply2_kernel<<<(Nn * F2 + 255) / 256, 256>>>(out, Nn * F2);
}

// round 6
// speedup vs baseline: 1.9723x; 1.0158x over previous
#include <cuda_runtime.h>
#include <cuda_bf16.h>
#include <cuda_fp16.h>
#include <stdint.h>

// ---------------------------------------------------------------------------
// Problem constants
// ---------------------------------------------------------------------------
#define NMAX 100000
#define EMAX 3200000
#define F0 512
#define F1 256
#define F2 64

// ---------------------------------------------------------------------------
// Static device scratch
// ---------------------------------------------------------------------------
__device__ float d_xw1[NMAX * F1];
__device__ float d_h[NMAX * F1];
__device__ float d_hw2[NMAX * F2];
__device__ int   d_cnt[NMAX];
__device__ int   d_fill[NMAX];
__device__ int   d_rowptr[NMAX + 1];
__device__ int   d_cols[EMAX];
__device__ float d_vals[EMAX];
__device__ int   d_chunksums[128];
__device__ float d_sum1[F1], d_sumsq1[F1], d_scale1[F1], d_bias1[F1];
__device__ float d_sum2[F2], d_sumsq2[F2], d_scale2[F2], d_bias2[F2];
// W1 split: hi/lo fp16, layout [N=256][K=512] K-major
__device__ __align__(128) __half d_Bh[F1 * F0];
__device__ __align__(128) __half d_Bl[F1 * F0];
// W2 split: hi/lo fp16, layout [N=64][K=256] K-major
__device__ __align__(128) __half d_B2h[F2 * F1];
__device__ __align__(128) __half d_B2l[F2 * F1];

// ---------------------------------------------------------------------------
// Helpers
// ---------------------------------------------------------------------------
__device__ __forceinline__ uint32_t smem_u32(const void* p) {
    uint32_t a;
    asm("{ .reg .u64 t; cvta.to.shared.u64 t, %1; cvt.u32.u64 %0, t; }" : "=r"(a) : "l"(p));
    return a;
}
__device__ __forceinline__ uint32_t pack2hi_h(float a, float b) {
    __half2 t = __floats2half2_rn(a, b);
    return *(uint32_t*)&t;
}
__device__ __forceinline__ uint32_t pack2lo_h(float a, float b) {
    float ah = __half2float(__float2half_rn(a));
    float bh = __half2float(__float2half_rn(b));
    __half2 t = __floats2half2_rn(a - ah, b - bh);
    return *(uint32_t*)&t;
}
__device__ __forceinline__ void mma_f16(float* d, const uint32_t* a, uint32_t b0, uint32_t b1) {
    asm volatile(
        "mma.sync.aligned.m16n8k16.row.col.f32.f16.f16.f32 "
        "{%0,%1,%2,%3}, {%4,%5,%6,%7}, {%8,%9}, {%0,%1,%2,%3};"
        : "+f"(d[0]), "+f"(d[1]), "+f"(d[2]), "+f"(d[3])
        : "r"(a[0]), "r"(a[1]), "r"(a[2]), "r"(a[3]), "r"(b0), "r"(b1));
}
__device__ __forceinline__ void ldmatrix_x4(uint32_t* r, uint32_t addr) {
    asm volatile("ldmatrix.sync.aligned.m8n8.x4.shared.b16 {%0,%1,%2,%3}, [%4];"
                 : "=r"(r[0]), "=r"(r[1]), "=r"(r[2]), "=r"(r[3]) : "r"(addr));
}
__device__ __forceinline__ void cp_async16(uint32_t saddr, const void* gptr) {
    asm volatile("cp.async.ca.shared.global [%0], [%1], 16;" :: "r"(saddr), "l"(gptr));
}
__device__ __forceinline__ void cp_commit() {
    asm volatile("cp.async.commit_group;" ::: "memory");
}
__device__ __forceinline__ void cp_wait0() {
    asm volatile("cp.async.wait_group 0;" ::: "memory");
}

// ---------------------------------------------------------------------------
// Zero transient accumulators
// ---------------------------------------------------------------------------
__global__ void zero_kernel(int Nn) {
    int i = blockIdx.x * blockDim.x + threadIdx.x;
    if (i < Nn) { d_cnt[i] = 0; d_fill[i] = 0; }
    if (i < F1) { d_sum1[i] = 0.f; d_sumsq1[i] = 0.f; }
    if (i < F2) { d_sum2[i] = 0.f; d_sumsq2[i] = 0.f; }
}

// ---------------------------------------------------------------------------
// CSR build
// ---------------------------------------------------------------------------
__global__ void hist_kernel(const int* __restrict__ erow, int E) {
    int i = blockIdx.x * blockDim.x + threadIdx.x;
    if (i < E) atomicAdd(&d_cnt[erow[i]], 1);
}

__global__ void scanA_kernel(int Nn) {
    __shared__ int sh[1024];
    int gid = blockIdx.x * 1024 + threadIdx.x;
    int v = (gid < Nn) ? d_cnt[gid] : 0;
    sh[threadIdx.x] = v;
    __syncthreads();
#pragma unroll
    for (int off = 1; off < 1024; off <<= 1) {
        int t = (threadIdx.x >= off) ? sh[threadIdx.x - off] : 0;
        __syncthreads();
        sh[threadIdx.x] += t;
        __syncthreads();
    }
    if (gid < Nn) d_rowptr[gid] = sh[threadIdx.x] - v;
    if (threadIdx.x == 1023) d_chunksums[blockIdx.x] = sh[1023];
}

__global__ void scanB_kernel(int nch) {
    __shared__ int sh[128];
    int v = (threadIdx.x < nch) ? d_chunksums[threadIdx.x] : 0;
    sh[threadIdx.x] = v;
    __syncthreads();
#pragma unroll
    for (int off = 1; off < 128; off <<= 1) {
        int t = (threadIdx.x >= off) ? sh[threadIdx.x - off] : 0;
        __syncthreads();
        sh[threadIdx.x] += t;
        __syncthreads();
    }
    if (threadIdx.x < nch) d_chunksums[threadIdx.x] = sh[threadIdx.x] - v;
}

__global__ void scanC_kernel(int Nn, int E) {
    int gid = blockIdx.x * blockDim.x + threadIdx.x;
    if (gid < Nn) d_rowptr[gid] += d_chunksums[gid >> 10];
    if (gid == 0) d_rowptr[Nn] = E;
}

__global__ void scatter_kernel(const int* __restrict__ erow,
                               const int* __restrict__ ecol,
                               const float* __restrict__ eval, int E) {
    int i = blockIdx.x * blockDim.x + threadIdx.x;
    if (i < E) {
        int r = erow[i];
        int p = d_rowptr[r] + atomicAdd(&d_fill[r], 1);
        d_cols[p] = ecol[i];
        d_vals[p] = eval[i];
    }
}

// ---------------------------------------------------------------------------
// Weight prep: split W into fp16 hi + lo, transposed to K-major
// ---------------------------------------------------------------------------
__global__ void prepW1_kernel(const float* __restrict__ W1) {
    int i = blockIdx.x * blockDim.x + threadIdx.x;
    if (i >= F0 * F1) return;
    int k = i >> 8;        // 0..511
    int n = i & 255;       // 0..255
    float w = W1[i];
    __half h = __float2half_rn(w);
    __half l = __float2half_rn(w - __half2float(h));
    d_Bh[(size_t)n * F0 + k] = h;
    d_Bl[(size_t)n * F0 + k] = l;
}
__global__ void prepW2_kernel(const float* __restrict__ W2) {
    int i = blockIdx.x * blockDim.x + threadIdx.x;
    if (i >= F1 * F2) return;
    int k = i >> 6;        // 0..255
    int n = i & 63;        // 0..63
    float w = W2[i];
    __half h = __float2half_rn(w);
    __half l = __float2half_rn(w - __half2float(h));
    d_B2h[(size_t)n * F1 + k] = h;
    d_B2l[(size_t)n * F1 + k] = l;
}

// ---------------------------------------------------------------------------
// GEMM1 via mma.sync fp16 3-term: Ahi*Bhi + Alo*Bhi + Ahi*Blo
// Block tile 128x128; warp tile 32x64 (4x2 warps); 16 k-blocks of 32 fp32 cols.
// Per k-block: x read once -> packed to A_hi/A_lo; B_hi/B_lo via cp.async.
// Buffer: A_hi 0 | A_lo 10240 | B_hi 20480 | B_lo 30720. Double-buffered.
// ---------------------------------------------------------------------------
#define PITCHB 80
#define BUFS1 40960
#define SMEM1 (2 * BUFS1)
#define KBLK1 16

__global__ void __launch_bounds__(256, 2)
gemm1_mma_kernel(const float* __restrict__ x, int M) {
    extern __shared__ __align__(16) char sm[];
    const int tid = threadIdx.x;
    const int wid = tid >> 5;
    const int lane = tid & 31;
    const int warp_m = wid & 3;
    const int warp_n = wid >> 2;
    const int gid = lane >> 2;
    const int tg = lane & 3;
    const int bm0 = blockIdx.x * 128;
    const int bn0 = blockIdx.y * 128;
    const uint32_t sb = smem_u32(sm);

    float acc[2][8][4];
#pragma unroll
    for (int mt = 0; mt < 2; mt++)
#pragma unroll
        for (int nt = 0; nt < 8; nt++)
#pragma unroll
            for (int q = 0; q < 4; q++) acc[mt][nt][q] = 0.f;

    const int arow = tid >> 3;
    const int af4 = tid & 7;
    const int brow = tid >> 2;
    const int bq = tid & 3;

    // ---- prologue: k-block 0
    {
#pragma unroll
        for (int i = 0; i < 4; i++) {
            int row = arow + i * 32;
            int rg = bm0 + row;
            float4 f = make_float4(0.f, 0.f, 0.f, 0.f);
            if (rg < M) f = *(const float4*)(x + (size_t)rg * F0 + af4 * 4);
            *(uint2*)(sm + row * PITCHB + af4 * 8) =
                make_uint2(pack2hi_h(f.x, f.y), pack2hi_h(f.z, f.w));
            *(uint2*)(sm + 10240 + row * PITCHB + af4 * 8) =
                make_uint2(pack2lo_h(f.x, f.y), pack2lo_h(f.z, f.w));
        }
#pragma unroll
        for (int i = 0; i < 2; i++) {
            int row = brow + i * 64;
            cp_async16(sb + 20480 + row * PITCHB + bq * 16,
                       d_Bh + (size_t)(bn0 + row) * F0 + bq * 8);
            cp_async16(sb + 30720 + row * PITCHB + bq * 16,
                       d_Bl + (size_t)(bn0 + row) * F0 + bq * 8);
        }
        cp_commit();
        cp_wait0();
        __syncthreads();
    }

    for (int c = 0; c < KBLK1; c++) {
        const int buf = c & 1;
        float4 fa[4];
        const bool have = (c + 1 < KBLK1);
        if (have) {
            const int sk0 = (c + 1) * 32;
#pragma unroll
            for (int i = 0; i < 4; i++) {
                int row = arow + i * 32;
                int rg = bm0 + row;
                fa[i] = make_float4(0.f, 0.f, 0.f, 0.f);
                if (rg < M) fa[i] = *(const float4*)(x + (size_t)rg * F0 + sk0 + af4 * 4);
            }
            const uint32_t bb = sb + (buf ^ 1) * BUFS1;
#pragma unroll
            for (int i = 0; i < 2; i++) {
                int row = brow + i * 64;
                cp_async16(bb + 20480 + row * PITCHB + bq * 16,
                           d_Bh + (size_t)(bn0 + row) * F0 + sk0 + bq * 8);
                cp_async16(bb + 30720 + row * PITCHB + bq * 16,
                           d_Bl + (size_t)(bn0 + row) * F0 + sk0 + bq * 8);
            }
            cp_commit();
        }
        // ---- compute on buf
        const uint32_t sA = sb + buf * BUFS1;
        const char* Bh = sm + buf * BUFS1 + 20480;
        const char* Bl = sm + buf * BUFS1 + 30720;
#pragma unroll
        for (int ks = 0; ks < 2; ks++) {
            uint32_t ahi[2][4], alo[2][4];
#pragma unroll
            for (int mt = 0; mt < 2; mt++) {
                uint32_t rowoff = (warp_m * 32 + mt * 16 + (lane & 15)) * PITCHB
                                  + ks * 32 + (lane >> 4) * 16;
                ldmatrix_x4(ahi[mt], sA + rowoff);
                ldmatrix_x4(alo[mt], sA + 10240 + rowoff);
            }
#pragma unroll
            for (int nt = 0; nt < 8; nt++) {
                uint32_t roff = (warp_n * 64 + nt * 8 + gid) * PITCHB + ks * 32 + tg * 4;
                uint32_t bh0 = *(const uint32_t*)(Bh + roff);
                uint32_t bh1 = *(const uint32_t*)(Bh + roff + 16);
                uint32_t bl0 = *(const uint32_t*)(Bl + roff);
                uint32_t bl1 = *(const uint32_t*)(Bl + roff + 16);
                mma_f16(acc[0][nt], ahi[0], bh0, bh1);
                mma_f16(acc[1][nt], ahi[1], bh0, bh1);
                mma_f16(acc[0][nt], alo[0], bh0, bh1);
                mma_f16(acc[1][nt], alo[1], bh0, bh1);
                mma_f16(acc[0][nt], ahi[0], bl0, bl1);
                mma_f16(acc[1][nt], ahi[1], bl0, bl1);
            }
        }
        // ---- commit staged A to the other buffer
        if (have) {
            char* dA = sm + (buf ^ 1) * BUFS1;
#pragma unroll
            for (int i = 0; i < 4; i++) {
                int row = arow + i * 32;
                *(uint2*)(dA + row * PITCHB + af4 * 8) =
                    make_uint2(pack2hi_h(fa[i].x, fa[i].y), pack2hi_h(fa[i].z, fa[i].w));
                *(uint2*)(dA + 10240 + row * PITCHB + af4 * 8) =
                    make_uint2(pack2lo_h(fa[i].x, fa[i].y), pack2lo_h(fa[i].z, fa[i].w));
            }
        }
        cp_wait0();
        __syncthreads();
    }

    // ---- epilogue
#pragma unroll
    for (int mt = 0; mt < 2; mt++) {
        int r0 = bm0 + warp_m * 32 + mt * 16 + gid;
        int r1 = r0 + 8;
#pragma unroll
        for (int nt = 0; nt < 8; nt++) {
            int col = bn0 + warp_n * 64 + nt * 8 + tg * 2;
            if (r0 < M)
                *(float2*)(d_xw1 + (size_t)r0 * F1 + col) =
                    make_float2(acc[mt][nt][0], acc[mt][nt][1]);
            if (r1 < M)
                *(float2*)(d_xw1 + (size_t)r1 * F1 + col) =
                    make_float2(acc[mt][nt][2], acc[mt][nt][3]);
        }
    }
}

// ---------------------------------------------------------------------------
// GEMM2 via mma.sync fp16 3-term: hw2 = relu(bn1(h)) @ W2
// Block tile 128x64; 8 warps, warp tile 16x64; 8 k-blocks of 32 fp32 cols.
// Buffer: A_hi 0 | A_lo 10240 | B_hi 20480 | B_lo 25600.
// ---------------------------------------------------------------------------
#define BUFS2 30720
#define SMEM2 (2 * BUFS2)
#define KBLK2 8

__global__ void __launch_bounds__(256, 2)
gemm2_mma_kernel(int M) {
    extern __shared__ __align__(16) char sm[];
    __shared__ float s_sc[F1], s_bi[F1];
    const int tid = threadIdx.x;
    const int wid = tid >> 5;
    const int lane = tid & 31;
    const int gid = lane >> 2;
    const int tg = lane & 3;
    const int bm0 = blockIdx.x * 128;
    const uint32_t sb = smem_u32(sm);

    s_sc[tid] = d_scale1[tid];
    s_bi[tid] = d_bias1[tid];
    __syncthreads();

    float acc[8][4];
#pragma unroll
    for (int nt = 0; nt < 8; nt++)
#pragma unroll
        for (int q = 0; q < 4; q++) acc[nt][q] = 0.f;

    const int arow = tid >> 3;
    const int af4 = tid & 7;
    const int brow = tid >> 2;   // 0..63
    const int bq = tid & 3;

    auto packA = [&](char* dst, int sk0) {
#pragma unroll
        for (int i = 0; i < 4; i++) {
            int row = arow + i * 32;
            int rg = bm0 + row;
            float4 f = make_float4(0.f, 0.f, 0.f, 0.f);
            if (rg < M) {
                f = *(const float4*)(d_h + (size_t)rg * F1 + sk0 + af4 * 4);
                int cb = sk0 + af4 * 4;
                f.x = fmaxf(fmaf(f.x, s_sc[cb + 0], s_bi[cb + 0]), 0.f);
                f.y = fmaxf(fmaf(f.y, s_sc[cb + 1], s_bi[cb + 1]), 0.f);
                f.z = fmaxf(fmaf(f.z, s_sc[cb + 2], s_bi[cb + 2]), 0.f);
                f.w = fmaxf(fmaf(f.w, s_sc[cb + 3], s_bi[cb + 3]), 0.f);
            }
            *(uint2*)(dst + row * PITCHB + af4 * 8) =
                make_uint2(pack2hi_h(f.x, f.y), pack2hi_h(f.z, f.w));
            *(uint2*)(dst + 10240 + row * PITCHB + af4 * 8) =
                make_uint2(pack2lo_h(f.x, f.y), pack2lo_h(f.z, f.w));
        }
    };

    // ---- prologue
    packA(sm, 0);
    cp_async16(sb + 20480 + brow * PITCHB + bq * 16, d_B2h + (size_t)brow * F1 + bq * 8);
    cp_async16(sb + 25600 + brow * PITCHB + bq * 16, d_B2l + (size_t)brow * F1 + bq * 8);
    cp_commit();
    cp_wait0();
    __syncthreads();

    for (int c = 0; c < KBLK2; c++) {
        const int buf = c & 1;
        const bool have = (c + 1 < KBLK2);
        if (have) {
            const int sk0 = (c + 1) * 32;
            const uint32_t bb = sb + (buf ^ 1) * BUFS2;
            cp_async16(bb + 20480 + brow * PITCHB + bq * 16,
                       d_B2h + (size_t)brow * F1 + sk0 + bq * 8);
            cp_async16(bb + 25600 + brow * PITCHB + bq * 16,
                       d_B2l + (size_t)brow * F1 + sk0 + bq * 8);
            cp_commit();
        }
        const uint32_t sA = sb + buf * BUFS2;
        const char* Bh = sm + buf * BUFS2 + 20480;
        const char* Bl = sm + buf * BUFS2 + 25600;
#pragma unroll
        for (int ks = 0; ks < 2; ks++) {
            uint32_t ahi[4], alo[4];
            uint32_t rowoff = (wid * 16 + (lane & 15)) * PITCHB + ks * 32 + (lane >> 4) * 16;
            ldmatrix_x4(ahi, sA + rowoff);
            ldmatrix_x4(alo, sA + 10240 + rowoff);
#pragma unroll
            for (int nt = 0; nt < 8; nt++) {
                uint32_t roff = (nt * 8 + gid) * PITCHB + ks * 32 + tg * 4;
                uint32_t bh0 = *(const uint32_t*)(Bh + roff);
                uint32_t bh1 = *(const uint32_t*)(Bh + roff + 16);
                uint32_t bl0 = *(const uint32_t*)(Bl + roff);
                uint32_t bl1 = *(const uint32_t*)(Bl + roff + 16);
                mma_f16(acc[nt], ahi, bh0, bh1);
                mma_f16(acc[nt], alo, bh0, bh1);
                mma_f16(acc[nt], ahi, bl0, bl1);
            }
        }
        if (have) packA(sm + (buf ^ 1) * BUFS2, (c + 1) * 32);
        cp_wait0();
        __syncthreads();
    }

    // ---- epilogue
    int r0 = bm0 + wid * 16 + gid;
    int r1 = r0 + 8;
#pragma unroll
    for (int nt = 0; nt < 8; nt++) {
        int col = nt * 8 + tg * 2;
        if (r0 < M)
            *(float2*)(d_hw2 + (size_t)r0 * F2 + col) = make_float2(acc[nt][0], acc[nt][1]);
        if (r1 < M)
            *(float2*)(d_hw2 + (size_t)r1 * F2 + col) = make_float2(acc[nt][2], acc[nt][3]);
    }
}

// ---------------------------------------------------------------------------
// SpMM1 (persistent): h = relu(A_sparse @ xw1), warp-per-row, edge batching,
// fused BN1 stats (register accumulators -> smem reduce -> global atomics).
// ---------------------------------------------------------------------------
__global__ void __launch_bounds__(256) spmm1_kernel(int Nn) {
    __shared__ float redS[8 * 256];
    __shared__ float redQ[8 * 256];
    const int tid = threadIdx.x;
    const int lane = tid & 31;
    const int wloc = tid >> 5;

    float bs[8], bq2[8];
#pragma unroll
    for (int k = 0; k < 8; k++) { bs[k] = 0.f; bq2[k] = 0.f; }

    for (int row = blockIdx.x * 8 + wloc; row < Nn; row += gridDim.x * 8) {
        int s = d_rowptr[row], e = d_rowptr[row + 1];
        float4 a0 = make_float4(0.f, 0.f, 0.f, 0.f);
        float4 a1 = make_float4(0.f, 0.f, 0.f, 0.f);
        for (int base = s; base < e; base += 32) {
            int take = min(32, e - base);
            int cc = 0; float vv = 0.f;
            if (lane < take) { cc = __ldg(&d_cols[base + lane]); vv = __ldg(&d_vals[base + lane]); }
            if (take == 32) {
#pragma unroll 4
                for (int j = 0; j < 32; j++) {
                    int c = __shfl_sync(0xffffffffu, cc, j);
                    float v = __shfl_sync(0xffffffffu, vv, j);
                    const float4* p = (const float4*)(d_xw1 + (size_t)c * F1);
                    float4 x0 = __ldg(&p[lane]);
                    float4 x1 = __ldg(&p[lane + 32]);
                    a0.x = fmaf(v, x0.x, a0.x); a0.y = fmaf(v, x0.y, a0.y);
                    a0.z = fmaf(v, x0.z, a0.z); a0.w = fmaf(v, x0.w, a0.w);
                    a1.x = fmaf(v, x1.x, a1.x); a1.y = fmaf(v, x1.y, a1.y);
                    a1.z = fmaf(v, x1.z, a1.z); a1.w = fmaf(v, x1.w, a1.w);
                }
            } else {
                for (int j = 0; j < take; j++) {
                    int c = __shfl_sync(0xffffffffu, cc, j);
                    float v = __shfl_sync(0xffffffffu, vv, j);
                    const float4* p = (const float4*)(d_xw1 + (size_t)c * F1);
                    float4 x0 = __ldg(&p[lane]);
                    float4 x1 = __ldg(&p[lane + 32]);
                    a0.x = fmaf(v, x0.x, a0.x); a0.y = fmaf(v, x0.y, a0.y);
                    a0.z = fmaf(v, x0.z, a0.z); a0.w = fmaf(v, x0.w, a0.w);
                    a1.x = fmaf(v, x1.x, a1.x); a1.y = fmaf(v, x1.y, a1.y);
                    a1.z = fmaf(v, x1.z, a1.z); a1.w = fmaf(v, x1.w, a1.w);
                }
            }
        }
        a0 = make_float4(fmaxf(a0.x, 0.f), fmaxf(a0.y, 0.f), fmaxf(a0.z, 0.f), fmaxf(a0.w, 0.f));
        a1 = make_float4(fmaxf(a1.x, 0.f), fmaxf(a1.y, 0.f), fmaxf(a1.z, 0.f), fmaxf(a1.w, 0.f));
        float4* o = (float4*)(d_h + (size_t)row * F1);
        o[lane] = a0;
        o[lane + 32] = a1;
        bs[0] += a0.x; bs[1] += a0.y; bs[2] += a0.z; bs[3] += a0.w;
        bs[4] += a1.x; bs[5] += a1.y; bs[6] += a1.z; bs[7] += a1.w;
        bq2[0] = fmaf(a0.x, a0.x, bq2[0]); bq2[1] = fmaf(a0.y, a0.y, bq2[1]);
        bq2[2] = fmaf(a0.z, a0.z, bq2[2]); bq2[3] = fmaf(a0.w, a0.w, bq2[3]);
        bq2[4] = fmaf(a1.x, a1.x, bq2[4]); bq2[5] = fmaf(a1.y, a1.y, bq2[5]);
        bq2[6] = fmaf(a1.z, a1.z, bq2[6]); bq2[7] = fmaf(a1.w, a1.w, bq2[7]);
    }
    // block reduction of BN1 partials
    int base = wloc * 256 + lane * 8;
#pragma unroll
    for (int k = 0; k < 8; k++) { redS[base + k] = bs[k]; redQ[base + k] = bq2[k]; }
    __syncthreads();
    {
        int c = tid;                         // column 0..255
        int l = (c & 127) >> 2;
        int k = ((c >> 7) << 2) | (c & 3);
        float s = 0.f, q = 0.f;
#pragma unroll
        for (int w = 0; w < 8; w++) {
            s += redS[w * 256 + l * 8 + k];
            q += redQ[w * 256 + l * 8 + k];
        }
        atomicAdd(&d_sum1[c], s);
        atomicAdd(&d_sumsq1[c], q);
    }
}

// ---------------------------------------------------------------------------
// SpMM2 (persistent): out = relu(A_sparse @ hw2), fused BN2 stats.
// ---------------------------------------------------------------------------
__global__ void __launch_bounds__(256) spmm2_kernel(float* __restrict__ out, int Nn) {
    __shared__ float redS[8 * 64];
    __shared__ float redQ[8 * 64];
    const int tid = threadIdx.x;
    const int lane = tid & 31;
    const int wloc = tid >> 5;

    float bs0 = 0.f, bs1 = 0.f, bq0 = 0.f, bq1 = 0.f;

    for (int row = blockIdx.x * 8 + wloc; row < Nn; row += gridDim.x * 8) {
        int s = d_rowptr[row], e = d_rowptr[row + 1];
        float2 acc = make_float2(0.f, 0.f);
        for (int base = s; base < e; base += 32) {
            int take = min(32, e - base);
            int cc = 0; float vv = 0.f;
            if (lane < take) { cc = __ldg(&d_cols[base + lane]); vv = __ldg(&d_vals[base + lane]); }
            if (take == 32) {
#pragma unroll 4
                for (int j = 0; j < 32; j++) {
                    int c = __shfl_sync(0xffffffffu, cc, j);
                    float v = __shfl_sync(0xffffffffu, vv, j);
                    const float2* p = (const float2*)(d_hw2 + (size_t)c * F2);
                    float2 x0 = __ldg(&p[lane]);
                    acc.x = fmaf(v, x0.x, acc.x);
                    acc.y = fmaf(v, x0.y, acc.y);
                }
            } else {
                for (int j = 0; j < take; j++) {
                    int c = __shfl_sync(0xffffffffu, cc, j);
                    float v = __shfl_sync(0xffffffffu, vv, j);
                    const float2* p = (const float2*)(d_hw2 + (size_t)c * F2);
                    float2 x0 = __ldg(&p[lane]);
                    acc.x = fmaf(v, x0.x, acc.x);
                    acc.y = fmaf(v, x0.y, acc.y);
                }
            }
        }
        acc.x = fmaxf(acc.x, 0.f);
        acc.y = fmaxf(acc.y, 0.f);
        ((float2*)(out + (size_t)row * F2))[lane] = acc;
        bs0 += acc.x; bs1 += acc.y;
        bq0 = fmaf(acc.x, acc.x, bq0);
        bq1 = fmaf(acc.y, acc.y, bq1);
    }
    int base = wloc * 64 + lane * 2;
    redS[base] = bs0; redS[base + 1] = bs1;
    redQ[base] = bq0; redQ[base + 1] = bq1;
    __syncthreads();
    if (tid < 64) {
        float s = 0.f, q = 0.f;
#pragma unroll
        for (int w = 0; w < 8; w++) {
            s += redS[w * 64 + tid];
            q += redQ[w * 64 + tid];
        }
        atomicAdd(&d_sum2[tid], s);
        atomicAdd(&d_sumsq2[tid], q);
    }
}

// ---------------------------------------------------------------------------
// BN finalize + BN2 apply
// ---------------------------------------------------------------------------
__global__ void bnfin_kernel(const float* __restrict__ sum, const float* __restrict__ sumsq,
                             const float* __restrict__ gamma, const float* __restrict__ beta,
                             float* __restrict__ scale, float* __restrict__ bias,
                             int Nn, int F) {
    int c = threadIdx.x;
    if (c >= F) return;
    float inv = 1.f / (float)Nn;
    float mean = sum[c] * inv;
    float var = sumsq[c] * inv - mean * mean;
    float rs = rsqrtf(var + 1e-5f);
    float sc = gamma[c] * rs;
    scale[c] = sc;
    bias[c] = beta[c] - mean * sc;
}

__global__ void bnapply2_kernel(float* __restrict__ out, int total) {
    int i = blockIdx.x * blockDim.x + threadIdx.x;
    if (i < total) {
        int c = i & (F2 - 1);
        out[i] = fmaf(out[i], d_scale2[c], d_bias2[c]);
    }
}

// ---------------------------------------------------------------------------
// Launch sequence: CSR build forked onto a side stream, joined before SpMM1.
// ---------------------------------------------------------------------------
extern "C" void kernel_launch(void* const* d_in, const int* in_sizes, int n_in,
                              void* d_out, int out_size) {
    const float* x    = (const float*)d_in[0];
    const int*   erow = (const int*)d_in[1];
    const int*   ecol = (const int*)d_in[2];
    const float* evl  = (const float*)d_in[3];
    const float* W1   = (const float*)d_in[4];
    const float* g1   = (const float*)d_in[5];
    const float* b1   = (const float*)d_in[6];
    const float* W2   = (const float*)d_in[7];
    const float* g2   = (const float*)d_in[8];
    const float* b2   = (const float*)d_in[9];
    float* out = (float*)d_out;

    const int Nn = in_sizes[0] / F0;   // 100000
    const int E  = in_sizes[1];        // 3200000
    const int nch = (Nn + 1023) / 1024;

    float* p_sum1   = nullptr; cudaGetSymbolAddress((void**)&p_sum1,   d_sum1);
    float* p_sumsq1 = nullptr; cudaGetSymbolAddress((void**)&p_sumsq1, d_sumsq1);
    float* p_scale1 = nullptr; cudaGetSymbolAddress((void**)&p_scale1, d_scale1);
    float* p_bias1  = nullptr; cudaGetSymbolAddress((void**)&p_bias1,  d_bias1);
    float* p_sum2   = nullptr; cudaGetSymbolAddress((void**)&p_sum2,   d_sum2);
    float* p_sumsq2 = nullptr; cudaGetSymbolAddress((void**)&p_sumsq2, d_sumsq2);
    float* p_scale2 = nullptr; cudaGetSymbolAddress((void**)&p_scale2, d_scale2);
    float* p_bias2  = nullptr; cudaGetSymbolAddress((void**)&p_bias2,  d_bias2);

    static cudaStream_t s2 = nullptr;
    static cudaEvent_t evFork = nullptr, evJoin = nullptr;
    static int attr_done = 0;
    if (!attr_done) {
        cudaFuncSetAttribute(gemm1_mma_kernel,
                             cudaFuncAttributeMaxDynamicSharedMemorySize, SMEM1);
        cudaFuncSetAttribute(gemm2_mma_kernel,
                             cudaFuncAttributeMaxDynamicSharedMemorySize, SMEM2);
        cudaStreamCreateWithFlags(&s2, cudaStreamNonBlocking);
        cudaEventCreateWithFlags(&evFork, cudaEventDisableTiming);
        cudaEventCreateWithFlags(&evJoin, cudaEventDisableTiming);
        attr_done = 1;
    }

    // ---- fork: CSR build on s2, GEMM1 path on main stream
    cudaEventRecord(evFork, 0);
    cudaStreamWaitEvent(s2, evFork, 0);

    zero_kernel<<<(Nn + 255) / 256, 256, 0, s2>>>(Nn);
    hist_kernel<<<(E + 255) / 256, 256, 0, s2>>>(erow, E);
    scanA_kernel<<<nch, 1024, 0, s2>>>(Nn);
    scanB_kernel<<<1, 128, 0, s2>>>(nch);
    scanC_kernel<<<(Nn + 255) / 256, 256, 0, s2>>>(Nn, E);
    scatter_kernel<<<(E + 255) / 256, 256, 0, s2>>>(erow, ecol, evl, E);
    cudaEventRecord(evJoin, s2);

    prepW1_kernel<<<(F0 * F1 + 255) / 256, 256>>>(W1);
    prepW2_kernel<<<(F1 * F2 + 255) / 256, 256>>>(W2);
    gemm1_mma_kernel<<<dim3((Nn + 127) / 128, 2), 256, SMEM1>>>(x, Nn);

    // ---- join
    cudaStreamWaitEvent(0, evJoin, 0);

    // Layer 1
    spmm1_kernel<<<1184, 256>>>(Nn);
    bnfin_kernel<<<1, F1>>>(p_sum1, p_sumsq1, g1, b1, p_scale1, p_bias1, Nn, F1);

    // Layer 2
    gemm2_mma_kernel<<<(Nn + 127) / 128, 256, SMEM2>>>(Nn);
    spmm2_kernel<<<1184, 256>>>(out, Nn);
    bnfin_kernel<<<1, F2>>>(p_sum2, p_sumsq2, g2, b2, p_scale2, p_bias2, Nn, F2);
    bnapply2_kernel<<<(Nn * F2 + 255) / 256, 256>>>(out, Nn * F2);
}